// round 9
// baseline (speedup 1.0000x reference)
#include <cuda_runtime.h>
#include <math_constants.h>
#include <cstdint>

// Problem constants
constexpr int Bc = 4;
constexpr int Nn = 1024;
constexpr int Cc = 1024;
constexpr int Hh = 16;
constexpr int Dd = 64;          // head dim
constexpr int BH = Bc * Hh;     // 64
constexpr int M1 = Bc * Nn;     // 4096 rows of x
constexpr int NQKV = 3 * Cc;    // 3072

constexpr size_t QKV_ELEMS = (size_t)BH * Nn * Dd;   // 4,194,304 per tensor
constexpr size_t OUT_ELEMS = (size_t)Bc * Nn * Cc;   // 4,194,304

// Scratch (device globals — no allocations allowed)
__device__ float g_q[QKV_ELEMS];
__device__ float g_k[QKV_ELEMS];
__device__ float g_v[QKV_ELEMS];
__device__ float g_oh[OUT_ELEMS];   // merged heads [B, N, C]

// ---------------------------------------------------------------------------
// TF32 helpers: 3xTF32 decomposition for fp32-accurate tensor-core GEMM.
// ---------------------------------------------------------------------------
__device__ __forceinline__ uint32_t cvt_tf32(float x) {
    uint32_t r;
    asm("cvt.rna.tf32.f32 %0, %1;" : "=r"(r) : "f"(x));
    return r;
}
__device__ __forceinline__ void split_tf32(float x, uint32_t& h, uint32_t& l) {
    h = cvt_tf32(x);
    l = cvt_tf32(x - __uint_as_float(h));
}
__device__ __forceinline__ void split4(float4 v, uint4& h, uint4& l) {
    split_tf32(v.x, h.x, l.x);
    split_tf32(v.y, h.y, l.y);
    split_tf32(v.z, h.z, l.z);
    split_tf32(v.w, h.w, l.w);
}
__device__ __forceinline__ void mma8(float* d,
                                     uint32_t a0, uint32_t a1, uint32_t a2, uint32_t a3,
                                     uint32_t b0, uint32_t b1) {
    asm volatile(
        "mma.sync.aligned.m16n8k8.row.col.f32.tf32.tf32.f32 "
        "{%0,%1,%2,%3}, {%4,%5,%6,%7}, {%8,%9}, {%0,%1,%2,%3};\n"
        : "+f"(d[0]), "+f"(d[1]), "+f"(d[2]), "+f"(d[3])
        : "r"(a0), "r"(a1), "r"(a2), "r"(a3), "r"(b0), "r"(b1));
}

// ---------------------------------------------------------------------------
// Kernel 1: QKV GEMM (3xTF32).  X[4096,1024] @ W[1024,3072] + b ->
// scatter into Q(scaled)/K/V laid out [BH, N, HD].
// Block tile 128x128, BK=16, 256 threads (8 warps, 2x4), warp tile 64x32.
// ---------------------------------------------------------------------------
__device__ __forceinline__ void qkv_store(int m, int n, float v,
                                          const float* __restrict__ bias) {
    v += __ldg(bias + n);
    const int b = m >> 10, nn = m & 1023;
    const int part = n >> 10, w = n & 1023;
    const int h = w >> 6, d = w & 63;
    const size_t idx = (((size_t)(b * Hh + h)) * Nn + nn) * Dd + d;
    if (part == 0)      g_q[idx] = v * 0.125f;    // HD^-0.5
    else if (part == 1) g_k[idx] = v;
    else                g_v[idx] = v;
}

__global__ __launch_bounds__(256) void qkv_tc(const float* __restrict__ X,
                                              const float* __restrict__ W,
                                              const float* __restrict__ bias)
{
    __shared__ uint32_t AsH[128][20], AsL[128][20];
    __shared__ uint32_t BsH[16][136], BsL[16][136];
    const int tid = threadIdx.x;
    const int m0 = blockIdx.y * 128, n0 = blockIdx.x * 128;

    const int a_m = tid >> 2, a_k4 = tid & 3;     // A: rows a_m, a_m+64
    const int b_k = tid >> 5, b_n4 = tid & 31;    // B: rows b_k, b_k+8

    float4 ra0 = *(const float4*)(X + (size_t)(m0 + a_m) * Cc + a_k4 * 4);
    float4 ra1 = *(const float4*)(X + (size_t)(m0 + a_m + 64) * Cc + a_k4 * 4);
    float4 rb0 = *(const float4*)(W + (size_t)b_k * NQKV + n0 + b_n4 * 4);
    float4 rb1 = *(const float4*)(W + (size_t)(b_k + 8) * NQKV + n0 + b_n4 * 4);
    {
        uint4 h, l;
        split4(ra0, h, l); *(uint4*)&AsH[a_m][a_k4 * 4] = h;      *(uint4*)&AsL[a_m][a_k4 * 4] = l;
        split4(ra1, h, l); *(uint4*)&AsH[a_m + 64][a_k4 * 4] = h; *(uint4*)&AsL[a_m + 64][a_k4 * 4] = l;
        split4(rb0, h, l); *(uint4*)&BsH[b_k][b_n4 * 4] = h;      *(uint4*)&BsL[b_k][b_n4 * 4] = l;
        split4(rb1, h, l); *(uint4*)&BsH[b_k + 8][b_n4 * 4] = h;  *(uint4*)&BsL[b_k + 8][b_n4 * 4] = l;
    }
    __syncthreads();

    const int lane = tid & 31, wid = tid >> 5;
    const int grp = lane >> 2, t4 = lane & 3;
    const int wm = (wid >> 2) * 64, wn = (wid & 3) * 32;

    float acc[4][4][4];
#pragma unroll
    for (int i = 0; i < 4; i++)
#pragma unroll
        for (int j = 0; j < 4; j++)
#pragma unroll
            for (int c = 0; c < 4; c++) acc[i][j][c] = 0.0f;

#pragma unroll 1
    for (int k0 = 0; k0 < Cc; k0 += 16) {
        const bool nxt = (k0 + 16) < Cc;
        if (nxt) {
            ra0 = *(const float4*)(X + (size_t)(m0 + a_m) * Cc + k0 + 16 + a_k4 * 4);
            ra1 = *(const float4*)(X + (size_t)(m0 + a_m + 64) * Cc + k0 + 16 + a_k4 * 4);
            rb0 = *(const float4*)(W + (size_t)(k0 + 16 + b_k) * NQKV + n0 + b_n4 * 4);
            rb1 = *(const float4*)(W + (size_t)(k0 + 16 + b_k + 8) * NQKV + n0 + b_n4 * 4);
        }
#pragma unroll
        for (int kk = 0; kk < 2; kk++) {
            uint32_t bh[4][2], bl[4][2];
#pragma unroll
            for (int nt = 0; nt < 4; nt++) {
                const int n = wn + nt * 8 + grp;
                bh[nt][0] = BsH[kk * 8 + t4][n];     bh[nt][1] = BsH[kk * 8 + t4 + 4][n];
                bl[nt][0] = BsL[kk * 8 + t4][n];     bl[nt][1] = BsL[kk * 8 + t4 + 4][n];
            }
#pragma unroll
            for (int mt = 0; mt < 4; mt++) {
                const int r = wm + mt * 16 + grp;
                const uint32_t ah0 = AsH[r][kk * 8 + t4],     ah1 = AsH[r + 8][kk * 8 + t4];
                const uint32_t ah2 = AsH[r][kk * 8 + t4 + 4], ah3 = AsH[r + 8][kk * 8 + t4 + 4];
                const uint32_t al0 = AsL[r][kk * 8 + t4],     al1 = AsL[r + 8][kk * 8 + t4];
                const uint32_t al2 = AsL[r][kk * 8 + t4 + 4], al3 = AsL[r + 8][kk * 8 + t4 + 4];
#pragma unroll
                for (int nt = 0; nt < 4; nt++) {
                    mma8(acc[mt][nt], al0, al1, al2, al3, bh[nt][0], bh[nt][1]);
                    mma8(acc[mt][nt], ah0, ah1, ah2, ah3, bl[nt][0], bl[nt][1]);
                    mma8(acc[mt][nt], ah0, ah1, ah2, ah3, bh[nt][0], bh[nt][1]);
                }
            }
        }
        if (nxt) {
            __syncthreads();
            uint4 h, l;
            split4(ra0, h, l); *(uint4*)&AsH[a_m][a_k4 * 4] = h;      *(uint4*)&AsL[a_m][a_k4 * 4] = l;
            split4(ra1, h, l); *(uint4*)&AsH[a_m + 64][a_k4 * 4] = h; *(uint4*)&AsL[a_m + 64][a_k4 * 4] = l;
            split4(rb0, h, l); *(uint4*)&BsH[b_k][b_n4 * 4] = h;      *(uint4*)&BsL[b_k][b_n4 * 4] = l;
            split4(rb1, h, l); *(uint4*)&BsH[b_k + 8][b_n4 * 4] = h;  *(uint4*)&BsL[b_k + 8][b_n4 * 4] = l;
            __syncthreads();
        }
    }

#pragma unroll
    for (int mt = 0; mt < 4; mt++) {
        const int r = m0 + wm + mt * 16 + grp;
#pragma unroll
        for (int nt = 0; nt < 4; nt++) {
            const int c = n0 + wn + nt * 8 + t4 * 2;
            qkv_store(r,     c,     acc[mt][nt][0], bias);
            qkv_store(r,     c + 1, acc[mt][nt][1], bias);
            qkv_store(r + 8, c,     acc[mt][nt][2], bias);
            qkv_store(r + 8, c + 1, acc[mt][nt][3], bias);
        }
    }
}

// ---------------------------------------------------------------------------
// Kernel 2: logits (3xTF32) = Q @ K^T + int_matrix + (1-mask)*-1e9.
// Per (b,h): [1024,64]@[64,1024].  Block 128x128, K=64 in 4 stages of 16.
// ---------------------------------------------------------------------------
__global__ __launch_bounds__(256) void qk_tc(const float* __restrict__ IM,
                                             const float* __restrict__ MASK,
                                             float* __restrict__ attn)
{
    __shared__ uint32_t AsH[128][20], AsL[128][20];
    __shared__ uint32_t KsH[128][20], KsL[128][20];
    const int z = blockIdx.z;
    const int m0 = blockIdx.y * 128, n0 = blockIdx.x * 128;
    const float* Qb = g_q + (size_t)z * Nn * Dd;
    const float* Kb = g_k + (size_t)z * Nn * Dd;
    const int tid = threadIdx.x;

    const int a_m = tid >> 2, a_k4 = tid & 3;   // rows a_m, a_m+64 of the 128-tile

    float4 ra0 = *(const float4*)(Qb + (size_t)(m0 + a_m) * Dd + a_k4 * 4);
    float4 ra1 = *(const float4*)(Qb + (size_t)(m0 + a_m + 64) * Dd + a_k4 * 4);
    float4 rk0 = *(const float4*)(Kb + (size_t)(n0 + a_m) * Dd + a_k4 * 4);
    float4 rk1 = *(const float4*)(Kb + (size_t)(n0 + a_m + 64) * Dd + a_k4 * 4);
    {
        uint4 h, l;
        split4(ra0, h, l); *(uint4*)&AsH[a_m][a_k4 * 4] = h;      *(uint4*)&AsL[a_m][a_k4 * 4] = l;
        split4(ra1, h, l); *(uint4*)&AsH[a_m + 64][a_k4 * 4] = h; *(uint4*)&AsL[a_m + 64][a_k4 * 4] = l;
        split4(rk0, h, l); *(uint4*)&KsH[a_m][a_k4 * 4] = h;      *(uint4*)&KsL[a_m][a_k4 * 4] = l;
        split4(rk1, h, l); *(uint4*)&KsH[a_m + 64][a_k4 * 4] = h; *(uint4*)&KsL[a_m + 64][a_k4 * 4] = l;
    }
    __syncthreads();

    const int lane = tid & 31, wid = tid >> 5;
    const int grp = lane >> 2, t4 = lane & 3;
    const int wm = (wid >> 2) * 64, wn = (wid & 3) * 32;

    float acc[4][4][4];
#pragma unroll
    for (int i = 0; i < 4; i++)
#pragma unroll
        for (int j = 0; j < 4; j++)
#pragma unroll
            for (int c = 0; c < 4; c++) acc[i][j][c] = 0.0f;

#pragma unroll 1
    for (int k0 = 0; k0 < Dd; k0 += 16) {
        const bool nxt = (k0 + 16) < Dd;
        if (nxt) {
            ra0 = *(const float4*)(Qb + (size_t)(m0 + a_m) * Dd + k0 + 16 + a_k4 * 4);
            ra1 = *(const float4*)(Qb + (size_t)(m0 + a_m + 64) * Dd + k0 + 16 + a_k4 * 4);
            rk0 = *(const float4*)(Kb + (size_t)(n0 + a_m) * Dd + k0 + 16 + a_k4 * 4);
            rk1 = *(const float4*)(Kb + (size_t)(n0 + a_m + 64) * Dd + k0 + 16 + a_k4 * 4);
        }
#pragma unroll
        for (int kk = 0; kk < 2; kk++) {
            uint32_t bh[4][2], bl[4][2];
#pragma unroll
            for (int nt = 0; nt < 4; nt++) {
                const int n = wn + nt * 8 + grp;
                bh[nt][0] = KsH[n][kk * 8 + t4];     bh[nt][1] = KsH[n][kk * 8 + t4 + 4];
                bl[nt][0] = KsL[n][kk * 8 + t4];     bl[nt][1] = KsL[n][kk * 8 + t4 + 4];
            }
#pragma unroll
            for (int mt = 0; mt < 4; mt++) {
                const int r = wm + mt * 16 + grp;
                const uint32_t ah0 = AsH[r][kk * 8 + t4],     ah1 = AsH[r + 8][kk * 8 + t4];
                const uint32_t ah2 = AsH[r][kk * 8 + t4 + 4], ah3 = AsH[r + 8][kk * 8 + t4 + 4];
                const uint32_t al0 = AsL[r][kk * 8 + t4],     al1 = AsL[r + 8][kk * 8 + t4];
                const uint32_t al2 = AsL[r][kk * 8 + t4 + 4], al3 = AsL[r + 8][kk * 8 + t4 + 4];
#pragma unroll
                for (int nt = 0; nt < 4; nt++) {
                    mma8(acc[mt][nt], al0, al1, al2, al3, bh[nt][0], bh[nt][1]);
                    mma8(acc[mt][nt], ah0, ah1, ah2, ah3, bl[nt][0], bl[nt][1]);
                    mma8(acc[mt][nt], ah0, ah1, ah2, ah3, bh[nt][0], bh[nt][1]);
                }
            }
        }
        if (nxt) {
            __syncthreads();
            uint4 h, l;
            split4(ra0, h, l); *(uint4*)&AsH[a_m][a_k4 * 4] = h;      *(uint4*)&AsL[a_m][a_k4 * 4] = l;
            split4(ra1, h, l); *(uint4*)&AsH[a_m + 64][a_k4 * 4] = h; *(uint4*)&AsL[a_m + 64][a_k4 * 4] = l;
            split4(rk0, h, l); *(uint4*)&KsH[a_m][a_k4 * 4] = h;      *(uint4*)&KsL[a_m][a_k4 * 4] = l;
            split4(rk1, h, l); *(uint4*)&KsH[a_m + 64][a_k4 * 4] = h; *(uint4*)&KsL[a_m + 64][a_k4 * 4] = l;
            __syncthreads();
        }
    }

    const int b = z >> 4;
    const float* imz = IM + ((size_t)z << 20);
    const float* mkb = MASK + ((size_t)b << 20);
    float* az = attn + ((size_t)z << 20);
#pragma unroll
    for (int mt = 0; mt < 4; mt++) {
#pragma unroll
        for (int nt = 0; nt < 4; nt++) {
            const int c = n0 + wn + nt * 8 + t4 * 2;
#pragma unroll
            for (int half = 0; half < 2; half++) {
                const int r = m0 + wm + mt * 16 + grp + half * 8;
                const size_t off = ((size_t)r << 10) + c;
                const float2 im2 = *(const float2*)(imz + off);
                const float2 mk2 = *(const float2*)(mkb + off);
                float2 o;
                o.x = acc[mt][nt][half * 2 + 0] + im2.x + (1.0f - mk2.x) * -1e9f;
                o.y = acc[mt][nt][half * 2 + 1] + im2.y + (1.0f - mk2.y) * -1e9f;
                *(float2*)(az + off) = o;
            }
        }
    }
}

// ---------------------------------------------------------------------------
// Kernel 3: row softmax over 1024 elements, in place.  One block per row.
// ---------------------------------------------------------------------------
__device__ __forceinline__ float warpMax(float v) {
#pragma unroll
    for (int o = 16; o; o >>= 1) v = fmaxf(v, __shfl_xor_sync(0xffffffffu, v, o));
    return v;
}
__device__ __forceinline__ float warpSum(float v) {
#pragma unroll
    for (int o = 16; o; o >>= 1) v += __shfl_xor_sync(0xffffffffu, v, o);
    return v;
}

__global__ __launch_bounds__(256) void softmax_rows(float* __restrict__ attn)
{
    __shared__ float sm[8];
    __shared__ float ss[8];
    const size_t row = blockIdx.x;
    float4* p = (float4*)(attn + row * Nn);
    const int tid = threadIdx.x;
    const int lane = tid & 31, wid = tid >> 5;

    float4 v = p[tid];
    float m = fmaxf(fmaxf(v.x, v.y), fmaxf(v.z, v.w));
    m = warpMax(m);
    if (lane == 0) sm[wid] = m;
    __syncthreads();
    if (tid < 32) {
        float t = (tid < 8) ? sm[tid] : -CUDART_INF_F;
        t = warpMax(t);
        if (tid == 0) sm[0] = t;
    }
    __syncthreads();
    m = sm[0];

    float4 e;
    e.x = expf(v.x - m);
    e.y = expf(v.y - m);
    e.z = expf(v.z - m);
    e.w = expf(v.w - m);
    float s = e.x + e.y + e.z + e.w;
    s = warpSum(s);
    if (lane == 0) ss[wid] = s;
    __syncthreads();
    if (tid < 32) {
        float t = (tid < 8) ? ss[tid] : 0.0f;
        t = warpSum(t);
        if (tid == 0) ss[0] = t;
    }
    __syncthreads();
    const float inv = 1.0f / ss[0];
    e.x *= inv; e.y *= inv; e.z *= inv; e.w *= inv;
    p[tid] = e;
}

// ---------------------------------------------------------------------------
// Kernel 4: out_heads = attn @ V (3xTF32).  Per (b,h): [1024,1024]@[1024,64].
// Block 128x64, BK=16, 8 warps (4x2), warp tile 32x32.
// ---------------------------------------------------------------------------
__global__ __launch_bounds__(256) void av_tc(const float* __restrict__ attn)
{
    __shared__ uint32_t AsH[128][20], AsL[128][20];
    __shared__ uint32_t BsH[16][72], BsL[16][72];
    const int z = blockIdx.y;
    const int r0 = blockIdx.x * 128;
    const float* Ab = attn + ((size_t)z << 20);
    const float* Vb = g_v + (size_t)z * Nn * Dd;
    const int tid = threadIdx.x;

    const int a_m = tid >> 2, a_k4 = tid & 3;   // A rows a_m, a_m+64
    const int v_k = tid >> 4, v_n4 = tid & 15;  // V row v_k (16 rows x 16 float4)

    float4 ra0 = *(const float4*)(Ab + ((size_t)(r0 + a_m) << 10) + a_k4 * 4);
    float4 ra1 = *(const float4*)(Ab + ((size_t)(r0 + a_m + 64) << 10) + a_k4 * 4);
    float4 rb0 = *(const float4*)(Vb + (size_t)v_k * Dd + v_n4 * 4);
    {
        uint4 h, l;
        split4(ra0, h, l); *(uint4*)&AsH[a_m][a_k4 * 4] = h;      *(uint4*)&AsL[a_m][a_k4 * 4] = l;
        split4(ra1, h, l); *(uint4*)&AsH[a_m + 64][a_k4 * 4] = h; *(uint4*)&AsL[a_m + 64][a_k4 * 4] = l;
        split4(rb0, h, l); *(uint4*)&BsH[v_k][v_n4 * 4] = h;      *(uint4*)&BsL[v_k][v_n4 * 4] = l;
    }
    __syncthreads();

    const int lane = tid & 31, wid = tid >> 5;
    const int grp = lane >> 2, t4 = lane & 3;
    const int wm = (wid >> 1) * 32, wn = (wid & 1) * 32;

    float acc[2][4][4];
#pragma unroll
    for (int i = 0; i < 2; i++)
#pragma unroll
        for (int j = 0; j < 4; j++)
#pragma unroll
            for (int c = 0; c < 4; c++) acc[i][j][c] = 0.0f;

#pragma unroll 1
    for (int k0 = 0; k0 < Nn; k0 += 16) {
        const bool nxt = (k0 + 16) < Nn;
        if (nxt) {
            ra0 = *(const float4*)(Ab + ((size_t)(r0 + a_m) << 10) + k0 + 16 + a_k4 * 4);
            ra1 = *(const float4*)(Ab + ((size_t)(r0 + a_m + 64) << 10) + k0 + 16 + a_k4 * 4);
            rb0 = *(const float4*)(Vb + (size_t)(k0 + 16 + v_k) * Dd + v_n4 * 4);
        }
#pragma unroll
        for (int kk = 0; kk < 2; kk++) {
            uint32_t bh[4][2], bl[4][2];
#pragma unroll
            for (int nt = 0; nt < 4; nt++) {
                const int n = wn + nt * 8 + grp;
                bh[nt][0] = BsH[kk * 8 + t4][n];     bh[nt][1] = BsH[kk * 8 + t4 + 4][n];
                bl[nt][0] = BsL[kk * 8 + t4][n];     bl[nt][1] = BsL[kk * 8 + t4 + 4][n];
            }
#pragma unroll
            for (int mt = 0; mt < 2; mt++) {
                const int r = wm + mt * 16 + grp;
                const uint32_t ah0 = AsH[r][kk * 8 + t4],     ah1 = AsH[r + 8][kk * 8 + t4];
                const uint32_t ah2 = AsH[r][kk * 8 + t4 + 4], ah3 = AsH[r + 8][kk * 8 + t4 + 4];
                const uint32_t al0 = AsL[r][kk * 8 + t4],     al1 = AsL[r + 8][kk * 8 + t4];
                const uint32_t al2 = AsL[r][kk * 8 + t4 + 4], al3 = AsL[r + 8][kk * 8 + t4 + 4];
#pragma unroll
                for (int nt = 0; nt < 4; nt++) {
                    mma8(acc[mt][nt], al0, al1, al2, al3, bh[nt][0], bh[nt][1]);
                    mma8(acc[mt][nt], ah0, ah1, ah2, ah3, bl[nt][0], bl[nt][1]);
                    mma8(acc[mt][nt], ah0, ah1, ah2, ah3, bh[nt][0], bh[nt][1]);
                }
            }
        }
        if (nxt) {
            __syncthreads();
            uint4 h, l;
            split4(ra0, h, l); *(uint4*)&AsH[a_m][a_k4 * 4] = h;      *(uint4*)&AsL[a_m][a_k4 * 4] = l;
            split4(ra1, h, l); *(uint4*)&AsH[a_m + 64][a_k4 * 4] = h; *(uint4*)&AsL[a_m + 64][a_k4 * 4] = l;
            split4(rb0, h, l); *(uint4*)&BsH[v_k][v_n4 * 4] = h;      *(uint4*)&BsL[v_k][v_n4 * 4] = l;
            __syncthreads();
        }
    }

    const int b = z >> 4, h = z & 15;
#pragma unroll
    for (int mt = 0; mt < 2; mt++) {
#pragma unroll
        for (int nt = 0; nt < 4; nt++) {
            const int d = wn + nt * 8 + t4 * 2;
#pragma unroll
            for (int half = 0; half < 2; half++) {
                const int r = r0 + wm + mt * 16 + grp + half * 8;
                float2 o;
                o.x = acc[mt][nt][half * 2 + 0];
                o.y = acc[mt][nt][half * 2 + 1];
                *(float2*)(g_oh + ((size_t)(b * Nn + r) << 10) + h * Dd + d) = o;
            }
        }
    }
}

// ---------------------------------------------------------------------------
// Kernel 5: final projection (3xTF32).  OH[4096,1024] @ Wp[1024,1024] + bp.
// Same structure as kernel 1, N=1024.
// ---------------------------------------------------------------------------
__global__ __launch_bounds__(256) void proj_tc(const float* __restrict__ Wp,
                                               const float* __restrict__ bp,
                                               float* __restrict__ out)
{
    __shared__ uint32_t AsH[128][20], AsL[128][20];
    __shared__ uint32_t BsH[16][136], BsL[16][136];
    const int tid = threadIdx.x;
    const int m0 = blockIdx.y * 128, n0 = blockIdx.x * 128;

    const int a_m = tid >> 2, a_k4 = tid & 3;
    const int b_k = tid >> 5, b_n4 = tid & 31;

    float4 ra0 = *(const float4*)(g_oh + (size_t)(m0 + a_m) * Cc + a_k4 * 4);
    float4 ra1 = *(const float4*)(g_oh + (size_t)(m0 + a_m + 64) * Cc + a_k4 * 4);
    float4 rb0 = *(const float4*)(Wp + (size_t)b_k * Cc + n0 + b_n4 * 4);
    float4 rb1 = *(const float4*)(Wp + (size_t)(b_k + 8) * Cc + n0 + b_n4 * 4);
    {
        uint4 h, l;
        split4(ra0, h, l); *(uint4*)&AsH[a_m][a_k4 * 4] = h;      *(uint4*)&AsL[a_m][a_k4 * 4] = l;
        split4(ra1, h, l); *(uint4*)&AsH[a_m + 64][a_k4 * 4] = h; *(uint4*)&AsL[a_m + 64][a_k4 * 4] = l;
        split4(rb0, h, l); *(uint4*)&BsH[b_k][b_n4 * 4] = h;      *(uint4*)&BsL[b_k][b_n4 * 4] = l;
        split4(rb1, h, l); *(uint4*)&BsH[b_k + 8][b_n4 * 4] = h;  *(uint4*)&BsL[b_k + 8][b_n4 * 4] = l;
    }
    __syncthreads();

    const int lane = tid & 31, wid = tid >> 5;
    const int grp = lane >> 2, t4 = lane & 3;
    const int wm = (wid >> 2) * 64, wn = (wid & 3) * 32;

    float acc[4][4][4];
#pragma unroll
    for (int i = 0; i < 4; i++)
#pragma unroll
        for (int j = 0; j < 4; j++)
#pragma unroll
            for (int c = 0; c < 4; c++) acc[i][j][c] = 0.0f;

#pragma unroll 1
    for (int k0 = 0; k0 < Cc; k0 += 16) {
        const bool nxt = (k0 + 16) < Cc;
        if (nxt) {
            ra0 = *(const float4*)(g_oh + (size_t)(m0 + a_m) * Cc + k0 + 16 + a_k4 * 4);
            ra1 = *(const float4*)(g_oh + (size_t)(m0 + a_m + 64) * Cc + k0 + 16 + a_k4 * 4);
            rb0 = *(const float4*)(Wp + (size_t)(k0 + 16 + b_k) * Cc + n0 + b_n4 * 4);
            rb1 = *(const float4*)(Wp + (size_t)(k0 + 16 + b_k + 8) * Cc + n0 + b_n4 * 4);
        }
#pragma unroll
        for (int kk = 0; kk < 2; kk++) {
            uint32_t bh[4][2], bl[4][2];
#pragma unroll
            for (int nt = 0; nt < 4; nt++) {
                const int n = wn + nt * 8 + grp;
                bh[nt][0] = BsH[kk * 8 + t4][n];     bh[nt][1] = BsH[kk * 8 + t4 + 4][n];
                bl[nt][0] = BsL[kk * 8 + t4][n];     bl[nt][1] = BsL[kk * 8 + t4 + 4][n];
            }
#pragma unroll
            for (int mt = 0; mt < 4; mt++) {
                const int r = wm + mt * 16 + grp;
                const uint32_t ah0 = AsH[r][kk * 8 + t4],     ah1 = AsH[r + 8][kk * 8 + t4];
                const uint32_t ah2 = AsH[r][kk * 8 + t4 + 4], ah3 = AsH[r + 8][kk * 8 + t4 + 4];
                const uint32_t al0 = AsL[r][kk * 8 + t4],     al1 = AsL[r + 8][kk * 8 + t4];
                const uint32_t al2 = AsL[r][kk * 8 + t4 + 4], al3 = AsL[r + 8][kk * 8 + t4 + 4];
#pragma unroll
                for (int nt = 0; nt < 4; nt++) {
                    mma8(acc[mt][nt], al0, al1, al2, al3, bh[nt][0], bh[nt][1]);
                    mma8(acc[mt][nt], ah0, ah1, ah2, ah3, bl[nt][0], bl[nt][1]);
                    mma8(acc[mt][nt], ah0, ah1, ah2, ah3, bh[nt][0], bh[nt][1]);
                }
            }
        }
        if (nxt) {
            __syncthreads();
            uint4 h, l;
            split4(ra0, h, l); *(uint4*)&AsH[a_m][a_k4 * 4] = h;      *(uint4*)&AsL[a_m][a_k4 * 4] = l;
            split4(ra1, h, l); *(uint4*)&AsH[a_m + 64][a_k4 * 4] = h; *(uint4*)&AsL[a_m + 64][a_k4 * 4] = l;
            split4(rb0, h, l); *(uint4*)&BsH[b_k][b_n4 * 4] = h;      *(uint4*)&BsL[b_k][b_n4 * 4] = l;
            split4(rb1, h, l); *(uint4*)&BsH[b_k + 8][b_n4 * 4] = h;  *(uint4*)&BsL[b_k + 8][b_n4 * 4] = l;
            __syncthreads();
        }
    }

#pragma unroll
    for (int mt = 0; mt < 4; mt++) {
#pragma unroll
        for (int nt = 0; nt < 4; nt++) {
            const int c = n0 + wn + nt * 8 + t4 * 2;
#pragma unroll
            for (int half = 0; half < 2; half++) {
                const int r = m0 + wm + mt * 16 + grp + half * 8;
                float2 o;
                o.x = acc[mt][nt][half * 2 + 0] + __ldg(bp + c);
                o.y = acc[mt][nt][half * 2 + 1] + __ldg(bp + c + 1);
                *(float2*)(out + ((size_t)r << 10) + c) = o;
            }
        }
    }
}

// ---------------------------------------------------------------------------
extern "C" void kernel_launch(void* const* d_in, const int* in_sizes, int n_in,
                              void* d_out, int out_size)
{
    const float* x     = (const float*)d_in[0];  // [B,N,C]
    const float* im    = (const float*)d_in[1];  // [B,H,N,N]
    const float* mask  = (const float*)d_in[2];  // [B,1,N,N]
    const float* Wqkv  = (const float*)d_in[3];  // [C,3C]
    const float* bqkv  = (const float*)d_in[4];  // [3C]
    const float* Wproj = (const float*)d_in[5];  // [C,C]
    const float* bproj = (const float*)d_in[6];  // [C]

    float* out  = (float*)d_out;                 // [B,N,C]
    float* attn = out + OUT_ELEMS;               // [B,H,N,N]

    (void)in_sizes; (void)n_in; (void)out_size;

    qkv_tc<<<dim3(NQKV / 128, M1 / 128), 256>>>(x, Wqkv, bqkv);
    qk_tc<<<dim3(Nn / 128, Nn / 128, BH), 256>>>(im, mask, attn);
    softmax_rows<<<(unsigned)(BH * Nn), 256>>>(attn);
    av_tc<<<dim3(Nn / 128, BH), 256>>>(attn);
    proj_tc<<<dim3(Cc / 128, M1 / 128), 256>>>(Wproj, bproj, out);
}

// round 10
// speedup vs baseline: 1.0036x; 1.0036x over previous
#include <cuda_runtime.h>
#include <math_constants.h>
#include <cstdint>

// Problem constants
constexpr int Bc = 4;
constexpr int Nn = 1024;
constexpr int Cc = 1024;
constexpr int Hh = 16;
constexpr int Dd = 64;          // head dim
constexpr int BH = Bc * Hh;     // 64
constexpr int M1 = Bc * Nn;     // 4096 rows of x
constexpr int NQKV = 3 * Cc;    // 3072

constexpr size_t QKV_ELEMS = (size_t)BH * Nn * Dd;   // 4,194,304 per tensor
constexpr size_t OUT_ELEMS = (size_t)Bc * Nn * Cc;   // 4,194,304

// Scratch (device globals — no allocations allowed)
__device__ float g_q[QKV_ELEMS];
__device__ float g_k[QKV_ELEMS];
__device__ float g_v[QKV_ELEMS];
__device__ float g_oh[OUT_ELEMS];   // merged heads [B, N, C]

// ---------------------------------------------------------------------------
// TF32 helpers: 3xTF32 decomposition for fp32-accurate tensor-core GEMM.
// ---------------------------------------------------------------------------
__device__ __forceinline__ uint32_t cvt_tf32(float x) {
    uint32_t r;
    asm("cvt.rna.tf32.f32 %0, %1;" : "=r"(r) : "f"(x));
    return r;
}
__device__ __forceinline__ void split_tf32(float x, uint32_t& h, uint32_t& l) {
    h = cvt_tf32(x);
    l = cvt_tf32(x - __uint_as_float(h));
}
__device__ __forceinline__ void split4(float4 v, uint4& h, uint4& l) {
    split_tf32(v.x, h.x, l.x);
    split_tf32(v.y, h.y, l.y);
    split_tf32(v.z, h.z, l.z);
    split_tf32(v.w, h.w, l.w);
}
__device__ __forceinline__ void mma8(float* d,
                                     uint32_t a0, uint32_t a1, uint32_t a2, uint32_t a3,
                                     uint32_t b0, uint32_t b1) {
    asm volatile(
        "mma.sync.aligned.m16n8k8.row.col.f32.tf32.tf32.f32 "
        "{%0,%1,%2,%3}, {%4,%5,%6,%7}, {%8,%9}, {%0,%1,%2,%3};\n"
        : "+f"(d[0]), "+f"(d[1]), "+f"(d[2]), "+f"(d[3])
        : "r"(a0), "r"(a1), "r"(a2), "r"(a3), "r"(b0), "r"(b1));
}

// ---------------------------------------------------------------------------
// Kernel 1: QKV GEMM (3xTF32).  X[4096,1024] @ W[1024,3072] + b ->
// scatter into Q(scaled)/K/V laid out [BH, N, HD].
// Block tile 128x128, BK=16, 256 threads (8 warps, 2x4), warp tile 64x32.
// ---------------------------------------------------------------------------
__device__ __forceinline__ void qkv_store(int m, int n, float v,
                                          const float* __restrict__ bias) {
    v += __ldg(bias + n);
    const int b = m >> 10, nn = m & 1023;
    const int part = n >> 10, w = n & 1023;
    const int h = w >> 6, d = w & 63;
    const size_t idx = (((size_t)(b * Hh + h)) * Nn + nn) * Dd + d;
    if (part == 0)      g_q[idx] = v * 0.125f;    // HD^-0.5
    else if (part == 1) g_k[idx] = v;
    else                g_v[idx] = v;
}

__global__ __launch_bounds__(256) void qkv_tc(const float* __restrict__ X,
                                              const float* __restrict__ W,
                                              const float* __restrict__ bias)
{
    __shared__ uint32_t AsH[128][20], AsL[128][20];
    __shared__ uint32_t BsH[16][136], BsL[16][136];
    const int tid = threadIdx.x;
    const int m0 = blockIdx.y * 128, n0 = blockIdx.x * 128;

    const int a_m = tid >> 2, a_k4 = tid & 3;     // A: rows a_m, a_m+64
    const int b_k = tid >> 5, b_n4 = tid & 31;    // B: rows b_k, b_k+8

    float4 ra0 = *(const float4*)(X + (size_t)(m0 + a_m) * Cc + a_k4 * 4);
    float4 ra1 = *(const float4*)(X + (size_t)(m0 + a_m + 64) * Cc + a_k4 * 4);
    float4 rb0 = *(const float4*)(W + (size_t)b_k * NQKV + n0 + b_n4 * 4);
    float4 rb1 = *(const float4*)(W + (size_t)(b_k + 8) * NQKV + n0 + b_n4 * 4);
    {
        uint4 h, l;
        split4(ra0, h, l); *(uint4*)&AsH[a_m][a_k4 * 4] = h;      *(uint4*)&AsL[a_m][a_k4 * 4] = l;
        split4(ra1, h, l); *(uint4*)&AsH[a_m + 64][a_k4 * 4] = h; *(uint4*)&AsL[a_m + 64][a_k4 * 4] = l;
        split4(rb0, h, l); *(uint4*)&BsH[b_k][b_n4 * 4] = h;      *(uint4*)&BsL[b_k][b_n4 * 4] = l;
        split4(rb1, h, l); *(uint4*)&BsH[b_k + 8][b_n4 * 4] = h;  *(uint4*)&BsL[b_k + 8][b_n4 * 4] = l;
    }
    __syncthreads();

    const int lane = tid & 31, wid = tid >> 5;
    const int grp = lane >> 2, t4 = lane & 3;
    const int wm = (wid >> 2) * 64, wn = (wid & 3) * 32;

    float acc[4][4][4];
#pragma unroll
    for (int i = 0; i < 4; i++)
#pragma unroll
        for (int j = 0; j < 4; j++)
#pragma unroll
            for (int c = 0; c < 4; c++) acc[i][j][c] = 0.0f;

#pragma unroll 1
    for (int k0 = 0; k0 < Cc; k0 += 16) {
        const bool nxt = (k0 + 16) < Cc;
        if (nxt) {
            ra0 = *(const float4*)(X + (size_t)(m0 + a_m) * Cc + k0 + 16 + a_k4 * 4);
            ra1 = *(const float4*)(X + (size_t)(m0 + a_m + 64) * Cc + k0 + 16 + a_k4 * 4);
            rb0 = *(const float4*)(W + (size_t)(k0 + 16 + b_k) * NQKV + n0 + b_n4 * 4);
            rb1 = *(const float4*)(W + (size_t)(k0 + 16 + b_k + 8) * NQKV + n0 + b_n4 * 4);
        }
#pragma unroll
        for (int kk = 0; kk < 2; kk++) {
            uint32_t bh[4][2], bl[4][2];
#pragma unroll
            for (int nt = 0; nt < 4; nt++) {
                const int n = wn + nt * 8 + grp;
                bh[nt][0] = BsH[kk * 8 + t4][n];     bh[nt][1] = BsH[kk * 8 + t4 + 4][n];
                bl[nt][0] = BsL[kk * 8 + t4][n];     bl[nt][1] = BsL[kk * 8 + t4 + 4][n];
            }
#pragma unroll
            for (int mt = 0; mt < 4; mt++) {
                const int r = wm + mt * 16 + grp;
                const uint32_t ah0 = AsH[r][kk * 8 + t4],     ah1 = AsH[r + 8][kk * 8 + t4];
                const uint32_t ah2 = AsH[r][kk * 8 + t4 + 4], ah3 = AsH[r + 8][kk * 8 + t4 + 4];
                const uint32_t al0 = AsL[r][kk * 8 + t4],     al1 = AsL[r + 8][kk * 8 + t4];
                const uint32_t al2 = AsL[r][kk * 8 + t4 + 4], al3 = AsL[r + 8][kk * 8 + t4 + 4];
#pragma unroll
                for (int nt = 0; nt < 4; nt++) {
                    mma8(acc[mt][nt], al0, al1, al2, al3, bh[nt][0], bh[nt][1]);
                    mma8(acc[mt][nt], ah0, ah1, ah2, ah3, bl[nt][0], bl[nt][1]);
                    mma8(acc[mt][nt], ah0, ah1, ah2, ah3, bh[nt][0], bh[nt][1]);
                }
            }
        }
        if (nxt) {
            __syncthreads();
            uint4 h, l;
            split4(ra0, h, l); *(uint4*)&AsH[a_m][a_k4 * 4] = h;      *(uint4*)&AsL[a_m][a_k4 * 4] = l;
            split4(ra1, h, l); *(uint4*)&AsH[a_m + 64][a_k4 * 4] = h; *(uint4*)&AsL[a_m + 64][a_k4 * 4] = l;
            split4(rb0, h, l); *(uint4*)&BsH[b_k][b_n4 * 4] = h;      *(uint4*)&BsL[b_k][b_n4 * 4] = l;
            split4(rb1, h, l); *(uint4*)&BsH[b_k + 8][b_n4 * 4] = h;  *(uint4*)&BsL[b_k + 8][b_n4 * 4] = l;
            __syncthreads();
        }
    }

#pragma unroll
    for (int mt = 0; mt < 4; mt++) {
        const int r = m0 + wm + mt * 16 + grp;
#pragma unroll
        for (int nt = 0; nt < 4; nt++) {
            const int c = n0 + wn + nt * 8 + t4 * 2;
            qkv_store(r,     c,     acc[mt][nt][0], bias);
            qkv_store(r,     c + 1, acc[mt][nt][1], bias);
            qkv_store(r + 8, c,     acc[mt][nt][2], bias);
            qkv_store(r + 8, c + 1, acc[mt][nt][3], bias);
        }
    }
}

// ---------------------------------------------------------------------------
// Kernel 2: logits (3xTF32) = Q @ K^T + int_matrix + (1-mask)*-1e9.
// Per (b,h): [1024,64]@[64,1024].  Block 128x128, K=64 in 4 stages of 16.
// ---------------------------------------------------------------------------
__global__ __launch_bounds__(256) void qk_tc(const float* __restrict__ IM,
                                             const float* __restrict__ MASK,
                                             float* __restrict__ attn)
{
    __shared__ uint32_t AsH[128][20], AsL[128][20];
    __shared__ uint32_t KsH[128][20], KsL[128][20];
    const int z = blockIdx.z;
    const int m0 = blockIdx.y * 128, n0 = blockIdx.x * 128;
    const float* Qb = g_q + (size_t)z * Nn * Dd;
    const float* Kb = g_k + (size_t)z * Nn * Dd;
    const int tid = threadIdx.x;

    const int a_m = tid >> 2, a_k4 = tid & 3;   // rows a_m, a_m+64 of the 128-tile

    float4 ra0 = *(const float4*)(Qb + (size_t)(m0 + a_m) * Dd + a_k4 * 4);
    float4 ra1 = *(const float4*)(Qb + (size_t)(m0 + a_m + 64) * Dd + a_k4 * 4);
    float4 rk0 = *(const float4*)(Kb + (size_t)(n0 + a_m) * Dd + a_k4 * 4);
    float4 rk1 = *(const float4*)(Kb + (size_t)(n0 + a_m + 64) * Dd + a_k4 * 4);
    {
        uint4 h, l;
        split4(ra0, h, l); *(uint4*)&AsH[a_m][a_k4 * 4] = h;      *(uint4*)&AsL[a_m][a_k4 * 4] = l;
        split4(ra1, h, l); *(uint4*)&AsH[a_m + 64][a_k4 * 4] = h; *(uint4*)&AsL[a_m + 64][a_k4 * 4] = l;
        split4(rk0, h, l); *(uint4*)&KsH[a_m][a_k4 * 4] = h;      *(uint4*)&KsL[a_m][a_k4 * 4] = l;
        split4(rk1, h, l); *(uint4*)&KsH[a_m + 64][a_k4 * 4] = h; *(uint4*)&KsL[a_m + 64][a_k4 * 4] = l;
    }
    __syncthreads();

    const int lane = tid & 31, wid = tid >> 5;
    const int grp = lane >> 2, t4 = lane & 3;
    const int wm = (wid >> 2) * 64, wn = (wid & 3) * 32;

    float acc[4][4][4];
#pragma unroll
    for (int i = 0; i < 4; i++)
#pragma unroll
        for (int j = 0; j < 4; j++)
#pragma unroll
            for (int c = 0; c < 4; c++) acc[i][j][c] = 0.0f;

#pragma unroll 1
    for (int k0 = 0; k0 < Dd; k0 += 16) {
        const bool nxt = (k0 + 16) < Dd;
        if (nxt) {
            ra0 = *(const float4*)(Qb + (size_t)(m0 + a_m) * Dd + k0 + 16 + a_k4 * 4);
            ra1 = *(const float4*)(Qb + (size_t)(m0 + a_m + 64) * Dd + k0 + 16 + a_k4 * 4);
            rk0 = *(const float4*)(Kb + (size_t)(n0 + a_m) * Dd + k0 + 16 + a_k4 * 4);
            rk1 = *(const float4*)(Kb + (size_t)(n0 + a_m + 64) * Dd + k0 + 16 + a_k4 * 4);
        }
#pragma unroll
        for (int kk = 0; kk < 2; kk++) {
            uint32_t bh[4][2], bl[4][2];
#pragma unroll
            for (int nt = 0; nt < 4; nt++) {
                const int n = wn + nt * 8 + grp;
                bh[nt][0] = KsH[n][kk * 8 + t4];     bh[nt][1] = KsH[n][kk * 8 + t4 + 4];
                bl[nt][0] = KsL[n][kk * 8 + t4];     bl[nt][1] = KsL[n][kk * 8 + t4 + 4];
            }
#pragma unroll
            for (int mt = 0; mt < 4; mt++) {
                const int r = wm + mt * 16 + grp;
                const uint32_t ah0 = AsH[r][kk * 8 + t4],     ah1 = AsH[r + 8][kk * 8 + t4];
                const uint32_t ah2 = AsH[r][kk * 8 + t4 + 4], ah3 = AsH[r + 8][kk * 8 + t4 + 4];
                const uint32_t al0 = AsL[r][kk * 8 + t4],     al1 = AsL[r + 8][kk * 8 + t4];
                const uint32_t al2 = AsL[r][kk * 8 + t4 + 4], al3 = AsL[r + 8][kk * 8 + t4 + 4];
#pragma unroll
                for (int nt = 0; nt < 4; nt++) {
                    mma8(acc[mt][nt], al0, al1, al2, al3, bh[nt][0], bh[nt][1]);
                    mma8(acc[mt][nt], ah0, ah1, ah2, ah3, bl[nt][0], bl[nt][1]);
                    mma8(acc[mt][nt], ah0, ah1, ah2, ah3, bh[nt][0], bh[nt][1]);
                }
            }
        }
        if (nxt) {
            __syncthreads();
            uint4 h, l;
            split4(ra0, h, l); *(uint4*)&AsH[a_m][a_k4 * 4] = h;      *(uint4*)&AsL[a_m][a_k4 * 4] = l;
            split4(ra1, h, l); *(uint4*)&AsH[a_m + 64][a_k4 * 4] = h; *(uint4*)&AsL[a_m + 64][a_k4 * 4] = l;
            split4(rk0, h, l); *(uint4*)&KsH[a_m][a_k4 * 4] = h;      *(uint4*)&KsL[a_m][a_k4 * 4] = l;
            split4(rk1, h, l); *(uint4*)&KsH[a_m + 64][a_k4 * 4] = h; *(uint4*)&KsL[a_m + 64][a_k4 * 4] = l;
            __syncthreads();
        }
    }

    const int b = z >> 4;
    const float* imz = IM + ((size_t)z << 20);
    const float* mkb = MASK + ((size_t)b << 20);
    float* az = attn + ((size_t)z << 20);
#pragma unroll
    for (int mt = 0; mt < 4; mt++) {
#pragma unroll
        for (int nt = 0; nt < 4; nt++) {
            const int c = n0 + wn + nt * 8 + t4 * 2;
#pragma unroll
            for (int half = 0; half < 2; half++) {
                const int r = m0 + wm + mt * 16 + grp + half * 8;
                const size_t off = ((size_t)r << 10) + c;
                const float2 im2 = *(const float2*)(imz + off);
                const float2 mk2 = *(const float2*)(mkb + off);
                float2 o;
                o.x = acc[mt][nt][half * 2 + 0] + im2.x + (1.0f - mk2.x) * -1e9f;
                o.y = acc[mt][nt][half * 2 + 1] + im2.y + (1.0f - mk2.y) * -1e9f;
                *(float2*)(az + off) = o;
            }
        }
    }
}

// ---------------------------------------------------------------------------
// Kernel 3: row softmax over 1024 elements, in place.  One block per row.
// ---------------------------------------------------------------------------
__device__ __forceinline__ float warpMax(float v) {
#pragma unroll
    for (int o = 16; o; o >>= 1) v = fmaxf(v, __shfl_xor_sync(0xffffffffu, v, o));
    return v;
}
__device__ __forceinline__ float warpSum(float v) {
#pragma unroll
    for (int o = 16; o; o >>= 1) v += __shfl_xor_sync(0xffffffffu, v, o);
    return v;
}

__global__ __launch_bounds__(256) void softmax_rows(float* __restrict__ attn)
{
    __shared__ float sm[8];
    __shared__ float ss[8];
    const size_t row = blockIdx.x;
    float4* p = (float4*)(attn + row * Nn);
    const int tid = threadIdx.x;
    const int lane = tid & 31, wid = tid >> 5;

    float4 v = p[tid];
    float m = fmaxf(fmaxf(v.x, v.y), fmaxf(v.z, v.w));
    m = warpMax(m);
    if (lane == 0) sm[wid] = m;
    __syncthreads();
    if (tid < 32) {
        float t = (tid < 8) ? sm[tid] : -CUDART_INF_F;
        t = warpMax(t);
        if (tid == 0) sm[0] = t;
    }
    __syncthreads();
    m = sm[0];

    float4 e;
    e.x = expf(v.x - m);
    e.y = expf(v.y - m);
    e.z = expf(v.z - m);
    e.w = expf(v.w - m);
    float s = e.x + e.y + e.z + e.w;
    s = warpSum(s);
    if (lane == 0) ss[wid] = s;
    __syncthreads();
    if (tid < 32) {
        float t = (tid < 8) ? ss[tid] : 0.0f;
        t = warpSum(t);
        if (tid == 0) ss[0] = t;
    }
    __syncthreads();
    const float inv = 1.0f / ss[0];
    e.x *= inv; e.y *= inv; e.z *= inv; e.w *= inv;
    p[tid] = e;
}

// ---------------------------------------------------------------------------
// Kernel 4: out_heads = attn @ V (3xTF32).  Per (b,h): [1024,1024]@[1024,64].
// Block 128x64, BK=16, 8 warps (4x2), warp tile 32x32.
// ---------------------------------------------------------------------------
__global__ __launch_bounds__(256) void av_tc(const float* __restrict__ attn)
{
    __shared__ uint32_t AsH[128][20], AsL[128][20];
    __shared__ uint32_t BsH[16][72], BsL[16][72];
    const int z = blockIdx.y;
    const int r0 = blockIdx.x * 128;
    const float* Ab = attn + ((size_t)z << 20);
    const float* Vb = g_v + (size_t)z * Nn * Dd;
    const int tid = threadIdx.x;

    const int a_m = tid >> 2, a_k4 = tid & 3;   // A rows a_m, a_m+64
    const int v_k = tid >> 4, v_n4 = tid & 15;  // V row v_k (16 rows x 16 float4)

    float4 ra0 = *(const float4*)(Ab + ((size_t)(r0 + a_m) << 10) + a_k4 * 4);
    float4 ra1 = *(const float4*)(Ab + ((size_t)(r0 + a_m + 64) << 10) + a_k4 * 4);
    float4 rb0 = *(const float4*)(Vb + (size_t)v_k * Dd + v_n4 * 4);
    {
        uint4 h, l;
        split4(ra0, h, l); *(uint4*)&AsH[a_m][a_k4 * 4] = h;      *(uint4*)&AsL[a_m][a_k4 * 4] = l;
        split4(ra1, h, l); *(uint4*)&AsH[a_m + 64][a_k4 * 4] = h; *(uint4*)&AsL[a_m + 64][a_k4 * 4] = l;
        split4(rb0, h, l); *(uint4*)&BsH[v_k][v_n4 * 4] = h;      *(uint4*)&BsL[v_k][v_n4 * 4] = l;
    }
    __syncthreads();

    const int lane = tid & 31, wid = tid >> 5;
    const int grp = lane >> 2, t4 = lane & 3;
    const int wm = (wid >> 1) * 32, wn = (wid & 1) * 32;

    float acc[2][4][4];
#pragma unroll
    for (int i = 0; i < 2; i++)
#pragma unroll
        for (int j = 0; j < 4; j++)
#pragma unroll
            for (int c = 0; c < 4; c++) acc[i][j][c] = 0.0f;

#pragma unroll 1
    for (int k0 = 0; k0 < Nn; k0 += 16) {
        const bool nxt = (k0 + 16) < Nn;
        if (nxt) {
            ra0 = *(const float4*)(Ab + ((size_t)(r0 + a_m) << 10) + k0 + 16 + a_k4 * 4);
            ra1 = *(const float4*)(Ab + ((size_t)(r0 + a_m + 64) << 10) + k0 + 16 + a_k4 * 4);
            rb0 = *(const float4*)(Vb + (size_t)(k0 + 16 + v_k) * Dd + v_n4 * 4);
        }
#pragma unroll
        for (int kk = 0; kk < 2; kk++) {
            uint32_t bh[4][2], bl[4][2];
#pragma unroll
            for (int nt = 0; nt < 4; nt++) {
                const int n = wn + nt * 8 + grp;
                bh[nt][0] = BsH[kk * 8 + t4][n];     bh[nt][1] = BsH[kk * 8 + t4 + 4][n];
                bl[nt][0] = BsL[kk * 8 + t4][n];     bl[nt][1] = BsL[kk * 8 + t4 + 4][n];
            }
#pragma unroll
            for (int mt = 0; mt < 2; mt++) {
                const int r = wm + mt * 16 + grp;
                const uint32_t ah0 = AsH[r][kk * 8 + t4],     ah1 = AsH[r + 8][kk * 8 + t4];
                const uint32_t ah2 = AsH[r][kk * 8 + t4 + 4], ah3 = AsH[r + 8][kk * 8 + t4 + 4];
                const uint32_t al0 = AsL[r][kk * 8 + t4],     al1 = AsL[r + 8][kk * 8 + t4];
                const uint32_t al2 = AsL[r][kk * 8 + t4 + 4], al3 = AsL[r + 8][kk * 8 + t4 + 4];
#pragma unroll
                for (int nt = 0; nt < 4; nt++) {
                    mma8(acc[mt][nt], al0, al1, al2, al3, bh[nt][0], bh[nt][1]);
                    mma8(acc[mt][nt], ah0, ah1, ah2, ah3, bl[nt][0], bl[nt][1]);
                    mma8(acc[mt][nt], ah0, ah1, ah2, ah3, bh[nt][0], bh[nt][1]);
                }
            }
        }
        if (nxt) {
            __syncthreads();
            uint4 h, l;
            split4(ra0, h, l); *(uint4*)&AsH[a_m][a_k4 * 4] = h;      *(uint4*)&AsL[a_m][a_k4 * 4] = l;
            split4(ra1, h, l); *(uint4*)&AsH[a_m + 64][a_k4 * 4] = h; *(uint4*)&AsL[a_m + 64][a_k4 * 4] = l;
            split4(rb0, h, l); *(uint4*)&BsH[v_k][v_n4 * 4] = h;      *(uint4*)&BsL[v_k][v_n4 * 4] = l;
            __syncthreads();
        }
    }

    const int b = z >> 4, h = z & 15;
#pragma unroll
    for (int mt = 0; mt < 2; mt++) {
#pragma unroll
        for (int nt = 0; nt < 4; nt++) {
            const int d = wn + nt * 8 + t4 * 2;
#pragma unroll
            for (int half = 0; half < 2; half++) {
                const int r = r0 + wm + mt * 16 + grp + half * 8;
                float2 o;
                o.x = acc[mt][nt][half * 2 + 0];
                o.y = acc[mt][nt][half * 2 + 1];
                *(float2*)(g_oh + ((size_t)(b * Nn + r) << 10) + h * Dd + d) = o;
            }
        }
    }
}

// ---------------------------------------------------------------------------
// Kernel 5: final projection (3xTF32).  OH[4096,1024] @ Wp[1024,1024] + bp.
// Same structure as kernel 1, N=1024.
// ---------------------------------------------------------------------------
__global__ __launch_bounds__(256) void proj_tc(const float* __restrict__ Wp,
                                               const float* __restrict__ bp,
                                               float* __restrict__ out)
{
    __shared__ uint32_t AsH[128][20], AsL[128][20];
    __shared__ uint32_t BsH[16][136], BsL[16][136];
    const int tid = threadIdx.x;
    const int m0 = blockIdx.y * 128, n0 = blockIdx.x * 128;

    const int a_m = tid >> 2, a_k4 = tid & 3;
    const int b_k = tid >> 5, b_n4 = tid & 31;

    float4 ra0 = *(const float4*)(g_oh + (size_t)(m0 + a_m) * Cc + a_k4 * 4);
    float4 ra1 = *(const float4*)(g_oh + (size_t)(m0 + a_m + 64) * Cc + a_k4 * 4);
    float4 rb0 = *(const float4*)(Wp + (size_t)b_k * Cc + n0 + b_n4 * 4);
    float4 rb1 = *(const float4*)(Wp + (size_t)(b_k + 8) * Cc + n0 + b_n4 * 4);
    {
        uint4 h, l;
        split4(ra0, h, l); *(uint4*)&AsH[a_m][a_k4 * 4] = h;      *(uint4*)&AsL[a_m][a_k4 * 4] = l;
        split4(ra1, h, l); *(uint4*)&AsH[a_m + 64][a_k4 * 4] = h; *(uint4*)&AsL[a_m + 64][a_k4 * 4] = l;
        split4(rb0, h, l); *(uint4*)&BsH[b_k][b_n4 * 4] = h;      *(uint4*)&BsL[b_k][b_n4 * 4] = l;
        split4(rb1, h, l); *(uint4*)&BsH[b_k + 8][b_n4 * 4] = h;  *(uint4*)&BsL[b_k + 8][b_n4 * 4] = l;
    }
    __syncthreads();

    const int lane = tid & 31, wid = tid >> 5;
    const int grp = lane >> 2, t4 = lane & 3;
    const int wm = (wid >> 2) * 64, wn = (wid & 3) * 32;

    float acc[4][4][4];
#pragma unroll
    for (int i = 0; i < 4; i++)
#pragma unroll
        for (int j = 0; j < 4; j++)
#pragma unroll
            for (int c = 0; c < 4; c++) acc[i][j][c] = 0.0f;

#pragma unroll 1
    for (int k0 = 0; k0 < Cc; k0 += 16) {
        const bool nxt = (k0 + 16) < Cc;
        if (nxt) {
            ra0 = *(const float4*)(g_oh + (size_t)(m0 + a_m) * Cc + k0 + 16 + a_k4 * 4);
            ra1 = *(const float4*)(g_oh + (size_t)(m0 + a_m + 64) * Cc + k0 + 16 + a_k4 * 4);
            rb0 = *(const float4*)(Wp + (size_t)(k0 + 16 + b_k) * Cc + n0 + b_n4 * 4);
            rb1 = *(const float4*)(Wp + (size_t)(k0 + 16 + b_k + 8) * Cc + n0 + b_n4 * 4);
        }
#pragma unroll
        for (int kk = 0; kk < 2; kk++) {
            uint32_t bh[4][2], bl[4][2];
#pragma unroll
            for (int nt = 0; nt < 4; nt++) {
                const int n = wn + nt * 8 + grp;
                bh[nt][0] = BsH[kk * 8 + t4][n];     bh[nt][1] = BsH[kk * 8 + t4 + 4][n];
                bl[nt][0] = BsL[kk * 8 + t4][n];     bl[nt][1] = BsL[kk * 8 + t4 + 4][n];
            }
#pragma unroll
            for (int mt = 0; mt < 4; mt++) {
                const int r = wm + mt * 16 + grp;
                const uint32_t ah0 = AsH[r][kk * 8 + t4],     ah1 = AsH[r + 8][kk * 8 + t4];
                const uint32_t ah2 = AsH[r][kk * 8 + t4 + 4], ah3 = AsH[r + 8][kk * 8 + t4 + 4];
                const uint32_t al0 = AsL[r][kk * 8 + t4],     al1 = AsL[r + 8][kk * 8 + t4];
                const uint32_t al2 = AsL[r][kk * 8 + t4 + 4], al3 = AsL[r + 8][kk * 8 + t4 + 4];
#pragma unroll
                for (int nt = 0; nt < 4; nt++) {
                    mma8(acc[mt][nt], al0, al1, al2, al3, bh[nt][0], bh[nt][1]);
                    mma8(acc[mt][nt], ah0, ah1, ah2, ah3, bl[nt][0], bl[nt][1]);
                    mma8(acc[mt][nt], ah0, ah1, ah2, ah3, bh[nt][0], bh[nt][1]);
                }
            }
        }
        if (nxt) {
            __syncthreads();
            uint4 h, l;
            split4(ra0, h, l); *(uint4*)&AsH[a_m][a_k4 * 4] = h;      *(uint4*)&AsL[a_m][a_k4 * 4] = l;
            split4(ra1, h, l); *(uint4*)&AsH[a_m + 64][a_k4 * 4] = h; *(uint4*)&AsL[a_m + 64][a_k4 * 4] = l;
            split4(rb0, h, l); *(uint4*)&BsH[b_k][b_n4 * 4] = h;      *(uint4*)&BsL[b_k][b_n4 * 4] = l;
            split4(rb1, h, l); *(uint4*)&BsH[b_k + 8][b_n4 * 4] = h;  *(uint4*)&BsL[b_k + 8][b_n4 * 4] = l;
            __syncthreads();
        }
    }

#pragma unroll
    for (int mt = 0; mt < 4; mt++) {
#pragma unroll
        for (int nt = 0; nt < 4; nt++) {
            const int c = n0 + wn + nt * 8 + t4 * 2;
#pragma unroll
            for (int half = 0; half < 2; half++) {
                const int r = m0 + wm + mt * 16 + grp + half * 8;
                float2 o;
                o.x = acc[mt][nt][half * 2 + 0] + __ldg(bp + c);
                o.y = acc[mt][nt][half * 2 + 1] + __ldg(bp + c + 1);
                *(float2*)(out + ((size_t)r << 10) + c) = o;
            }
        }
    }
}

// ---------------------------------------------------------------------------
extern "C" void kernel_launch(void* const* d_in, const int* in_sizes, int n_in,
                              void* d_out, int out_size)
{
    const float* x     = (const float*)d_in[0];  // [B,N,C]
    const float* im    = (const float*)d_in[1];  // [B,H,N,N]
    const float* mask  = (const float*)d_in[2];  // [B,1,N,N]
    const float* Wqkv  = (const float*)d_in[3];  // [C,3C]
    const float* bqkv  = (const float*)d_in[4];  // [3C]
    const float* Wproj = (const float*)d_in[5];  // [C,C]
    const float* bproj = (const float*)d_in[6];  // [C]

    float* out  = (float*)d_out;                 // [B,N,C]
    float* attn = out + OUT_ELEMS;               // [B,H,N,N]

    (void)in_sizes; (void)n_in; (void)out_size;

    qkv_tc<<<dim3(NQKV / 128, M1 / 128), 256>>>(x, Wqkv, bqkv);
    qk_tc<<<dim3(Nn / 128, Nn / 128, BH), 256>>>(im, mask, attn);
    softmax_rows<<<(unsigned)(BH * Nn), 256>>>(attn);
    av_tc<<<dim3(Nn / 128, BH), 256>>>(attn);
    proj_tc<<<dim3(Cc / 128, M1 / 128), 256>>>(Wproj, bproj, out);
}

// round 11
// speedup vs baseline: 1.0045x; 1.0010x over previous
#include <cuda_runtime.h>
#include <math_constants.h>
#include <cstdint>

// Problem constants
constexpr int Bc = 4;
constexpr int Nn = 1024;
constexpr int Cc = 1024;
constexpr int Hh = 16;
constexpr int Dd = 64;          // head dim
constexpr int BH = Bc * Hh;     // 64
constexpr int M1 = Bc * Nn;     // 4096 rows of x
constexpr int NQKV = 3 * Cc;    // 3072

constexpr size_t QKV_ELEMS = (size_t)BH * Nn * Dd;   // 4,194,304 per tensor
constexpr size_t OUT_ELEMS = (size_t)Bc * Nn * Cc;   // 4,194,304

// Scratch (device globals — no allocations allowed)
__device__ float g_q[QKV_ELEMS];
__device__ float g_k[QKV_ELEMS];
__device__ float g_v[QKV_ELEMS];
__device__ float g_oh[OUT_ELEMS];   // merged heads [B, N, C]

// ---------------------------------------------------------------------------
// TF32 helpers: 3xTF32 decomposition for fp32-accurate tensor-core GEMM.
// ---------------------------------------------------------------------------
__device__ __forceinline__ uint32_t cvt_tf32(float x) {
    uint32_t r;
    asm("cvt.rna.tf32.f32 %0, %1;" : "=r"(r) : "f"(x));
    return r;
}
__device__ __forceinline__ void split_tf32(float x, uint32_t& h, uint32_t& l) {
    h = cvt_tf32(x);
    l = cvt_tf32(x - __uint_as_float(h));
}
__device__ __forceinline__ void split4(float4 v, uint4& h, uint4& l) {
    split_tf32(v.x, h.x, l.x);
    split_tf32(v.y, h.y, l.y);
    split_tf32(v.z, h.z, l.z);
    split_tf32(v.w, h.w, l.w);
}
__device__ __forceinline__ void mma8(float* d,
                                     uint32_t a0, uint32_t a1, uint32_t a2, uint32_t a3,
                                     uint32_t b0, uint32_t b1) {
    asm volatile(
        "mma.sync.aligned.m16n8k8.row.col.f32.tf32.tf32.f32 "
        "{%0,%1,%2,%3}, {%4,%5,%6,%7}, {%8,%9}, {%0,%1,%2,%3};\n"
        : "+f"(d[0]), "+f"(d[1]), "+f"(d[2]), "+f"(d[3])
        : "r"(a0), "r"(a1), "r"(a2), "r"(a3), "r"(b0), "r"(b1));
}

// ---------------------------------------------------------------------------
// Kernel 1: QKV GEMM (3xTF32).  X[4096,1024] @ W[1024,3072] + b ->
// scatter into Q(scaled)/K/V laid out [BH, N, HD].
// Block tile 128x128, BK=16, 256 threads (8 warps, 2x4), warp tile 64x32.
// ---------------------------------------------------------------------------
__device__ __forceinline__ void qkv_store(int m, int n, float v,
                                          const float* __restrict__ bias) {
    v += __ldg(bias + n);
    const int b = m >> 10, nn = m & 1023;
    const int part = n >> 10, w = n & 1023;
    const int h = w >> 6, d = w & 63;
    const size_t idx = (((size_t)(b * Hh + h)) * Nn + nn) * Dd + d;
    if (part == 0)      g_q[idx] = v * 0.125f;    // HD^-0.5
    else if (part == 1) g_k[idx] = v;
    else                g_v[idx] = v;
}

__global__ __launch_bounds__(256) void qkv_tc(const float* __restrict__ X,
                                              const float* __restrict__ W,
                                              const float* __restrict__ bias)
{
    __shared__ uint32_t AsH[128][20], AsL[128][20];
    __shared__ uint32_t BsH[16][136], BsL[16][136];
    const int tid = threadIdx.x;
    const int m0 = blockIdx.y * 128, n0 = blockIdx.x * 128;

    const int a_m = tid >> 2, a_k4 = tid & 3;     // A: rows a_m, a_m+64
    const int b_k = tid >> 5, b_n4 = tid & 31;    // B: rows b_k, b_k+8

    float4 ra0 = *(const float4*)(X + (size_t)(m0 + a_m) * Cc + a_k4 * 4);
    float4 ra1 = *(const float4*)(X + (size_t)(m0 + a_m + 64) * Cc + a_k4 * 4);
    float4 rb0 = *(const float4*)(W + (size_t)b_k * NQKV + n0 + b_n4 * 4);
    float4 rb1 = *(const float4*)(W + (size_t)(b_k + 8) * NQKV + n0 + b_n4 * 4);
    {
        uint4 h, l;
        split4(ra0, h, l); *(uint4*)&AsH[a_m][a_k4 * 4] = h;      *(uint4*)&AsL[a_m][a_k4 * 4] = l;
        split4(ra1, h, l); *(uint4*)&AsH[a_m + 64][a_k4 * 4] = h; *(uint4*)&AsL[a_m + 64][a_k4 * 4] = l;
        split4(rb0, h, l); *(uint4*)&BsH[b_k][b_n4 * 4] = h;      *(uint4*)&BsL[b_k][b_n4 * 4] = l;
        split4(rb1, h, l); *(uint4*)&BsH[b_k + 8][b_n4 * 4] = h;  *(uint4*)&BsL[b_k + 8][b_n4 * 4] = l;
    }
    __syncthreads();

    const int lane = tid & 31, wid = tid >> 5;
    const int grp = lane >> 2, t4 = lane & 3;
    const int wm = (wid >> 2) * 64, wn = (wid & 3) * 32;

    float acc[4][4][4];
#pragma unroll
    for (int i = 0; i < 4; i++)
#pragma unroll
        for (int j = 0; j < 4; j++)
#pragma unroll
            for (int c = 0; c < 4; c++) acc[i][j][c] = 0.0f;

#pragma unroll 1
    for (int k0 = 0; k0 < Cc; k0 += 16) {
        const bool nxt = (k0 + 16) < Cc;
        if (nxt) {
            ra0 = *(const float4*)(X + (size_t)(m0 + a_m) * Cc + k0 + 16 + a_k4 * 4);
            ra1 = *(const float4*)(X + (size_t)(m0 + a_m + 64) * Cc + k0 + 16 + a_k4 * 4);
            rb0 = *(const float4*)(W + (size_t)(k0 + 16 + b_k) * NQKV + n0 + b_n4 * 4);
            rb1 = *(const float4*)(W + (size_t)(k0 + 16 + b_k + 8) * NQKV + n0 + b_n4 * 4);
        }
#pragma unroll
        for (int kk = 0; kk < 2; kk++) {
            uint32_t bh[4][2], bl[4][2];
#pragma unroll
            for (int nt = 0; nt < 4; nt++) {
                const int n = wn + nt * 8 + grp;
                bh[nt][0] = BsH[kk * 8 + t4][n];     bh[nt][1] = BsH[kk * 8 + t4 + 4][n];
                bl[nt][0] = BsL[kk * 8 + t4][n];     bl[nt][1] = BsL[kk * 8 + t4 + 4][n];
            }
#pragma unroll
            for (int mt = 0; mt < 4; mt++) {
                const int r = wm + mt * 16 + grp;
                const uint32_t ah0 = AsH[r][kk * 8 + t4],     ah1 = AsH[r + 8][kk * 8 + t4];
                const uint32_t ah2 = AsH[r][kk * 8 + t4 + 4], ah3 = AsH[r + 8][kk * 8 + t4 + 4];
                const uint32_t al0 = AsL[r][kk * 8 + t4],     al1 = AsL[r + 8][kk * 8 + t4];
                const uint32_t al2 = AsL[r][kk * 8 + t4 + 4], al3 = AsL[r + 8][kk * 8 + t4 + 4];
#pragma unroll
                for (int nt = 0; nt < 4; nt++) {
                    mma8(acc[mt][nt], al0, al1, al2, al3, bh[nt][0], bh[nt][1]);
                    mma8(acc[mt][nt], ah0, ah1, ah2, ah3, bl[nt][0], bl[nt][1]);
                    mma8(acc[mt][nt], ah0, ah1, ah2, ah3, bh[nt][0], bh[nt][1]);
                }
            }
        }
        if (nxt) {
            __syncthreads();
            uint4 h, l;
            split4(ra0, h, l); *(uint4*)&AsH[a_m][a_k4 * 4] = h;      *(uint4*)&AsL[a_m][a_k4 * 4] = l;
            split4(ra1, h, l); *(uint4*)&AsH[a_m + 64][a_k4 * 4] = h; *(uint4*)&AsL[a_m + 64][a_k4 * 4] = l;
            split4(rb0, h, l); *(uint4*)&BsH[b_k][b_n4 * 4] = h;      *(uint4*)&BsL[b_k][b_n4 * 4] = l;
            split4(rb1, h, l); *(uint4*)&BsH[b_k + 8][b_n4 * 4] = h;  *(uint4*)&BsL[b_k + 8][b_n4 * 4] = l;
            __syncthreads();
        }
    }

#pragma unroll
    for (int mt = 0; mt < 4; mt++) {
        const int r = m0 + wm + mt * 16 + grp;
#pragma unroll
        for (int nt = 0; nt < 4; nt++) {
            const int c = n0 + wn + nt * 8 + t4 * 2;
            qkv_store(r,     c,     acc[mt][nt][0], bias);
            qkv_store(r,     c + 1, acc[mt][nt][1], bias);
            qkv_store(r + 8, c,     acc[mt][nt][2], bias);
            qkv_store(r + 8, c + 1, acc[mt][nt][3], bias);
        }
    }
}

// ---------------------------------------------------------------------------
// Kernel 2: logits (3xTF32) = Q @ K^T + int_matrix + (1-mask)*-1e9.
// Per (b,h): [1024,64]@[64,1024].  Block 128x128, K=64 in 4 stages of 16.
// ---------------------------------------------------------------------------
__global__ __launch_bounds__(256) void qk_tc(const float* __restrict__ IM,
                                             const float* __restrict__ MASK,
                                             float* __restrict__ attn)
{
    __shared__ uint32_t AsH[128][20], AsL[128][20];
    __shared__ uint32_t KsH[128][20], KsL[128][20];
    const int z = blockIdx.z;
    const int m0 = blockIdx.y * 128, n0 = blockIdx.x * 128;
    const float* Qb = g_q + (size_t)z * Nn * Dd;
    const float* Kb = g_k + (size_t)z * Nn * Dd;
    const int tid = threadIdx.x;

    const int a_m = tid >> 2, a_k4 = tid & 3;   // rows a_m, a_m+64 of the 128-tile

    float4 ra0 = *(const float4*)(Qb + (size_t)(m0 + a_m) * Dd + a_k4 * 4);
    float4 ra1 = *(const float4*)(Qb + (size_t)(m0 + a_m + 64) * Dd + a_k4 * 4);
    float4 rk0 = *(const float4*)(Kb + (size_t)(n0 + a_m) * Dd + a_k4 * 4);
    float4 rk1 = *(const float4*)(Kb + (size_t)(n0 + a_m + 64) * Dd + a_k4 * 4);
    {
        uint4 h, l;
        split4(ra0, h, l); *(uint4*)&AsH[a_m][a_k4 * 4] = h;      *(uint4*)&AsL[a_m][a_k4 * 4] = l;
        split4(ra1, h, l); *(uint4*)&AsH[a_m + 64][a_k4 * 4] = h; *(uint4*)&AsL[a_m + 64][a_k4 * 4] = l;
        split4(rk0, h, l); *(uint4*)&KsH[a_m][a_k4 * 4] = h;      *(uint4*)&KsL[a_m][a_k4 * 4] = l;
        split4(rk1, h, l); *(uint4*)&KsH[a_m + 64][a_k4 * 4] = h; *(uint4*)&KsL[a_m + 64][a_k4 * 4] = l;
    }
    __syncthreads();

    const int lane = tid & 31, wid = tid >> 5;
    const int grp = lane >> 2, t4 = lane & 3;
    const int wm = (wid >> 2) * 64, wn = (wid & 3) * 32;

    float acc[4][4][4];
#pragma unroll
    for (int i = 0; i < 4; i++)
#pragma unroll
        for (int j = 0; j < 4; j++)
#pragma unroll
            for (int c = 0; c < 4; c++) acc[i][j][c] = 0.0f;

#pragma unroll 1
    for (int k0 = 0; k0 < Dd; k0 += 16) {
        const bool nxt = (k0 + 16) < Dd;
        if (nxt) {
            ra0 = *(const float4*)(Qb + (size_t)(m0 + a_m) * Dd + k0 + 16 + a_k4 * 4);
            ra1 = *(const float4*)(Qb + (size_t)(m0 + a_m + 64) * Dd + k0 + 16 + a_k4 * 4);
            rk0 = *(const float4*)(Kb + (size_t)(n0 + a_m) * Dd + k0 + 16 + a_k4 * 4);
            rk1 = *(const float4*)(Kb + (size_t)(n0 + a_m + 64) * Dd + k0 + 16 + a_k4 * 4);
        }
#pragma unroll
        for (int kk = 0; kk < 2; kk++) {
            uint32_t bh[4][2], bl[4][2];
#pragma unroll
            for (int nt = 0; nt < 4; nt++) {
                const int n = wn + nt * 8 + grp;
                bh[nt][0] = KsH[n][kk * 8 + t4];     bh[nt][1] = KsH[n][kk * 8 + t4 + 4];
                bl[nt][0] = KsL[n][kk * 8 + t4];     bl[nt][1] = KsL[n][kk * 8 + t4 + 4];
            }
#pragma unroll
            for (int mt = 0; mt < 4; mt++) {
                const int r = wm + mt * 16 + grp;
                const uint32_t ah0 = AsH[r][kk * 8 + t4],     ah1 = AsH[r + 8][kk * 8 + t4];
                const uint32_t ah2 = AsH[r][kk * 8 + t4 + 4], ah3 = AsH[r + 8][kk * 8 + t4 + 4];
                const uint32_t al0 = AsL[r][kk * 8 + t4],     al1 = AsL[r + 8][kk * 8 + t4];
                const uint32_t al2 = AsL[r][kk * 8 + t4 + 4], al3 = AsL[r + 8][kk * 8 + t4 + 4];
#pragma unroll
                for (int nt = 0; nt < 4; nt++) {
                    mma8(acc[mt][nt], al0, al1, al2, al3, bh[nt][0], bh[nt][1]);
                    mma8(acc[mt][nt], ah0, ah1, ah2, ah3, bl[nt][0], bl[nt][1]);
                    mma8(acc[mt][nt], ah0, ah1, ah2, ah3, bh[nt][0], bh[nt][1]);
                }
            }
        }
        if (nxt) {
            __syncthreads();
            uint4 h, l;
            split4(ra0, h, l); *(uint4*)&AsH[a_m][a_k4 * 4] = h;      *(uint4*)&AsL[a_m][a_k4 * 4] = l;
            split4(ra1, h, l); *(uint4*)&AsH[a_m + 64][a_k4 * 4] = h; *(uint4*)&AsL[a_m + 64][a_k4 * 4] = l;
            split4(rk0, h, l); *(uint4*)&KsH[a_m][a_k4 * 4] = h;      *(uint4*)&KsL[a_m][a_k4 * 4] = l;
            split4(rk1, h, l); *(uint4*)&KsH[a_m + 64][a_k4 * 4] = h; *(uint4*)&KsL[a_m + 64][a_k4 * 4] = l;
            __syncthreads();
        }
    }

    const int b = z >> 4;
    const float* imz = IM + ((size_t)z << 20);
    const float* mkb = MASK + ((size_t)b << 20);
    float* az = attn + ((size_t)z << 20);
#pragma unroll
    for (int mt = 0; mt < 4; mt++) {
#pragma unroll
        for (int nt = 0; nt < 4; nt++) {
            const int c = n0 + wn + nt * 8 + t4 * 2;
#pragma unroll
            for (int half = 0; half < 2; half++) {
                const int r = m0 + wm + mt * 16 + grp + half * 8;
                const size_t off = ((size_t)r << 10) + c;
                const float2 im2 = *(const float2*)(imz + off);
                const float2 mk2 = *(const float2*)(mkb + off);
                float2 o;
                o.x = acc[mt][nt][half * 2 + 0] + im2.x + (1.0f - mk2.x) * -1e9f;
                o.y = acc[mt][nt][half * 2 + 1] + im2.y + (1.0f - mk2.y) * -1e9f;
                *(float2*)(az + off) = o;
            }
        }
    }
}

// ---------------------------------------------------------------------------
// Kernel 3: row softmax over 1024 elements, in place.  One block per row.
// ---------------------------------------------------------------------------
__device__ __forceinline__ float warpMax(float v) {
#pragma unroll
    for (int o = 16; o; o >>= 1) v = fmaxf(v, __shfl_xor_sync(0xffffffffu, v, o));
    return v;
}
__device__ __forceinline__ float warpSum(float v) {
#pragma unroll
    for (int o = 16; o; o >>= 1) v += __shfl_xor_sync(0xffffffffu, v, o);
    return v;
}

__global__ __launch_bounds__(256) void softmax_rows(float* __restrict__ attn)
{
    __shared__ float sm[8];
    __shared__ float ss[8];
    const size_t row = blockIdx.x;
    float4* p = (float4*)(attn + row * Nn);
    const int tid = threadIdx.x;
    const int lane = tid & 31, wid = tid >> 5;

    float4 v = p[tid];
    float m = fmaxf(fmaxf(v.x, v.y), fmaxf(v.z, v.w));
    m = warpMax(m);
    if (lane == 0) sm[wid] = m;
    __syncthreads();
    if (tid < 32) {
        float t = (tid < 8) ? sm[tid] : -CUDART_INF_F;
        t = warpMax(t);
        if (tid == 0) sm[0] = t;
    }
    __syncthreads();
    m = sm[0];

    float4 e;
    e.x = expf(v.x - m);
    e.y = expf(v.y - m);
    e.z = expf(v.z - m);
    e.w = expf(v.w - m);
    float s = e.x + e.y + e.z + e.w;
    s = warpSum(s);
    if (lane == 0) ss[wid] = s;
    __syncthreads();
    if (tid < 32) {
        float t = (tid < 8) ? ss[tid] : 0.0f;
        t = warpSum(t);
        if (tid == 0) ss[0] = t;
    }
    __syncthreads();
    const float inv = 1.0f / ss[0];
    e.x *= inv; e.y *= inv; e.z *= inv; e.w *= inv;
    p[tid] = e;
}

// ---------------------------------------------------------------------------
// Kernel 4: out_heads = attn @ V (3xTF32).  Per (b,h): [1024,1024]@[1024,64].
// Block 128x64, BK=16, 8 warps (4x2), warp tile 32x32.
// ---------------------------------------------------------------------------
__global__ __launch_bounds__(256) void av_tc(const float* __restrict__ attn)
{
    __shared__ uint32_t AsH[128][20], AsL[128][20];
    __shared__ uint32_t BsH[16][72], BsL[16][72];
    const int z = blockIdx.y;
    const int r0 = blockIdx.x * 128;
    const float* Ab = attn + ((size_t)z << 20);
    const float* Vb = g_v + (size_t)z * Nn * Dd;
    const int tid = threadIdx.x;

    const int a_m = tid >> 2, a_k4 = tid & 3;   // A rows a_m, a_m+64
    const int v_k = tid >> 4, v_n4 = tid & 15;  // V row v_k (16 rows x 16 float4)

    float4 ra0 = *(const float4*)(Ab + ((size_t)(r0 + a_m) << 10) + a_k4 * 4);
    float4 ra1 = *(const float4*)(Ab + ((size_t)(r0 + a_m + 64) << 10) + a_k4 * 4);
    float4 rb0 = *(const float4*)(Vb + (size_t)v_k * Dd + v_n4 * 4);
    {
        uint4 h, l;
        split4(ra0, h, l); *(uint4*)&AsH[a_m][a_k4 * 4] = h;      *(uint4*)&AsL[a_m][a_k4 * 4] = l;
        split4(ra1, h, l); *(uint4*)&AsH[a_m + 64][a_k4 * 4] = h; *(uint4*)&AsL[a_m + 64][a_k4 * 4] = l;
        split4(rb0, h, l); *(uint4*)&BsH[v_k][v_n4 * 4] = h;      *(uint4*)&BsL[v_k][v_n4 * 4] = l;
    }
    __syncthreads();

    const int lane = tid & 31, wid = tid >> 5;
    const int grp = lane >> 2, t4 = lane & 3;
    const int wm = (wid >> 1) * 32, wn = (wid & 1) * 32;

    float acc[2][4][4];
#pragma unroll
    for (int i = 0; i < 2; i++)
#pragma unroll
        for (int j = 0; j < 4; j++)
#pragma unroll
            for (int c = 0; c < 4; c++) acc[i][j][c] = 0.0f;

#pragma unroll 1
    for (int k0 = 0; k0 < Nn; k0 += 16) {
        const bool nxt = (k0 + 16) < Nn;
        if (nxt) {
            ra0 = *(const float4*)(Ab + ((size_t)(r0 + a_m) << 10) + k0 + 16 + a_k4 * 4);
            ra1 = *(const float4*)(Ab + ((size_t)(r0 + a_m + 64) << 10) + k0 + 16 + a_k4 * 4);
            rb0 = *(const float4*)(Vb + (size_t)(k0 + 16 + v_k) * Dd + v_n4 * 4);
        }
#pragma unroll
        for (int kk = 0; kk < 2; kk++) {
            uint32_t bh[4][2], bl[4][2];
#pragma unroll
            for (int nt = 0; nt < 4; nt++) {
                const int n = wn + nt * 8 + grp;
                bh[nt][0] = BsH[kk * 8 + t4][n];     bh[nt][1] = BsH[kk * 8 + t4 + 4][n];
                bl[nt][0] = BsL[kk * 8 + t4][n];     bl[nt][1] = BsL[kk * 8 + t4 + 4][n];
            }
#pragma unroll
            for (int mt = 0; mt < 2; mt++) {
                const int r = wm + mt * 16 + grp;
                const uint32_t ah0 = AsH[r][kk * 8 + t4],     ah1 = AsH[r + 8][kk * 8 + t4];
                const uint32_t ah2 = AsH[r][kk * 8 + t4 + 4], ah3 = AsH[r + 8][kk * 8 + t4 + 4];
                const uint32_t al0 = AsL[r][kk * 8 + t4],     al1 = AsL[r + 8][kk * 8 + t4];
                const uint32_t al2 = AsL[r][kk * 8 + t4 + 4], al3 = AsL[r + 8][kk * 8 + t4 + 4];
#pragma unroll
                for (int nt = 0; nt < 4; nt++) {
                    mma8(acc[mt][nt], al0, al1, al2, al3, bh[nt][0], bh[nt][1]);
                    mma8(acc[mt][nt], ah0, ah1, ah2, ah3, bl[nt][0], bl[nt][1]);
                    mma8(acc[mt][nt], ah0, ah1, ah2, ah3, bh[nt][0], bh[nt][1]);
                }
            }
        }
        if (nxt) {
            __syncthreads();
            uint4 h, l;
            split4(ra0, h, l); *(uint4*)&AsH[a_m][a_k4 * 4] = h;      *(uint4*)&AsL[a_m][a_k4 * 4] = l;
            split4(ra1, h, l); *(uint4*)&AsH[a_m + 64][a_k4 * 4] = h; *(uint4*)&AsL[a_m + 64][a_k4 * 4] = l;
            split4(rb0, h, l); *(uint4*)&BsH[v_k][v_n4 * 4] = h;      *(uint4*)&BsL[v_k][v_n4 * 4] = l;
            __syncthreads();
        }
    }

    const int b = z >> 4, h = z & 15;
#pragma unroll
    for (int mt = 0; mt < 2; mt++) {
#pragma unroll
        for (int nt = 0; nt < 4; nt++) {
            const int d = wn + nt * 8 + t4 * 2;
#pragma unroll
            for (int half = 0; half < 2; half++) {
                const int r = r0 + wm + mt * 16 + grp + half * 8;
                float2 o;
                o.x = acc[mt][nt][half * 2 + 0];
                o.y = acc[mt][nt][half * 2 + 1];
                *(float2*)(g_oh + ((size_t)(b * Nn + r) << 10) + h * Dd + d) = o;
            }
        }
    }
}

// ---------------------------------------------------------------------------
// Kernel 5: final projection (3xTF32).  OH[4096,1024] @ Wp[1024,1024] + bp.
// Same structure as kernel 1, N=1024.
// ---------------------------------------------------------------------------
__global__ __launch_bounds__(256) void proj_tc(const float* __restrict__ Wp,
                                               const float* __restrict__ bp,
                                               float* __restrict__ out)
{
    __shared__ uint32_t AsH[128][20], AsL[128][20];
    __shared__ uint32_t BsH[16][136], BsL[16][136];
    const int tid = threadIdx.x;
    const int m0 = blockIdx.y * 128, n0 = blockIdx.x * 128;

    const int a_m = tid >> 2, a_k4 = tid & 3;
    const int b_k = tid >> 5, b_n4 = tid & 31;

    float4 ra0 = *(const float4*)(g_oh + (size_t)(m0 + a_m) * Cc + a_k4 * 4);
    float4 ra1 = *(const float4*)(g_oh + (size_t)(m0 + a_m + 64) * Cc + a_k4 * 4);
    float4 rb0 = *(const float4*)(Wp + (size_t)b_k * Cc + n0 + b_n4 * 4);
    float4 rb1 = *(const float4*)(Wp + (size_t)(b_k + 8) * Cc + n0 + b_n4 * 4);
    {
        uint4 h, l;
        split4(ra0, h, l); *(uint4*)&AsH[a_m][a_k4 * 4] = h;      *(uint4*)&AsL[a_m][a_k4 * 4] = l;
        split4(ra1, h, l); *(uint4*)&AsH[a_m + 64][a_k4 * 4] = h; *(uint4*)&AsL[a_m + 64][a_k4 * 4] = l;
        split4(rb0, h, l); *(uint4*)&BsH[b_k][b_n4 * 4] = h;      *(uint4*)&BsL[b_k][b_n4 * 4] = l;
        split4(rb1, h, l); *(uint4*)&BsH[b_k + 8][b_n4 * 4] = h;  *(uint4*)&BsL[b_k + 8][b_n4 * 4] = l;
    }
    __syncthreads();

    const int lane = tid & 31, wid = tid >> 5;
    const int grp = lane >> 2, t4 = lane & 3;
    const int wm = (wid >> 2) * 64, wn = (wid & 3) * 32;

    float acc[4][4][4];
#pragma unroll
    for (int i = 0; i < 4; i++)
#pragma unroll
        for (int j = 0; j < 4; j++)
#pragma unroll
            for (int c = 0; c < 4; c++) acc[i][j][c] = 0.0f;

#pragma unroll 1
    for (int k0 = 0; k0 < Cc; k0 += 16) {
        const bool nxt = (k0 + 16) < Cc;
        if (nxt) {
            ra0 = *(const float4*)(g_oh + (size_t)(m0 + a_m) * Cc + k0 + 16 + a_k4 * 4);
            ra1 = *(const float4*)(g_oh + (size_t)(m0 + a_m + 64) * Cc + k0 + 16 + a_k4 * 4);
            rb0 = *(const float4*)(Wp + (size_t)(k0 + 16 + b_k) * Cc + n0 + b_n4 * 4);
            rb1 = *(const float4*)(Wp + (size_t)(k0 + 16 + b_k + 8) * Cc + n0 + b_n4 * 4);
        }
#pragma unroll
        for (int kk = 0; kk < 2; kk++) {
            uint32_t bh[4][2], bl[4][2];
#pragma unroll
            for (int nt = 0; nt < 4; nt++) {
                const int n = wn + nt * 8 + grp;
                bh[nt][0] = BsH[kk * 8 + t4][n];     bh[nt][1] = BsH[kk * 8 + t4 + 4][n];
                bl[nt][0] = BsL[kk * 8 + t4][n];     bl[nt][1] = BsL[kk * 8 + t4 + 4][n];
            }
#pragma unroll
            for (int mt = 0; mt < 4; mt++) {
                const int r = wm + mt * 16 + grp;
                const uint32_t ah0 = AsH[r][kk * 8 + t4],     ah1 = AsH[r + 8][kk * 8 + t4];
                const uint32_t ah2 = AsH[r][kk * 8 + t4 + 4], ah3 = AsH[r + 8][kk * 8 + t4 + 4];
                const uint32_t al0 = AsL[r][kk * 8 + t4],     al1 = AsL[r + 8][kk * 8 + t4];
                const uint32_t al2 = AsL[r][kk * 8 + t4 + 4], al3 = AsL[r + 8][kk * 8 + t4 + 4];
#pragma unroll
                for (int nt = 0; nt < 4; nt++) {
                    mma8(acc[mt][nt], al0, al1, al2, al3, bh[nt][0], bh[nt][1]);
                    mma8(acc[mt][nt], ah0, ah1, ah2, ah3, bl[nt][0], bl[nt][1]);
                    mma8(acc[mt][nt], ah0, ah1, ah2, ah3, bh[nt][0], bh[nt][1]);
                }
            }
        }
        if (nxt) {
            __syncthreads();
            uint4 h, l;
            split4(ra0, h, l); *(uint4*)&AsH[a_m][a_k4 * 4] = h;      *(uint4*)&AsL[a_m][a_k4 * 4] = l;
            split4(ra1, h, l); *(uint4*)&AsH[a_m + 64][a_k4 * 4] = h; *(uint4*)&AsL[a_m + 64][a_k4 * 4] = l;
            split4(rb0, h, l); *(uint4*)&BsH[b_k][b_n4 * 4] = h;      *(uint4*)&BsL[b_k][b_n4 * 4] = l;
            split4(rb1, h, l); *(uint4*)&BsH[b_k + 8][b_n4 * 4] = h;  *(uint4*)&BsL[b_k + 8][b_n4 * 4] = l;
            __syncthreads();
        }
    }

#pragma unroll
    for (int mt = 0; mt < 4; mt++) {
#pragma unroll
        for (int nt = 0; nt < 4; nt++) {
            const int c = n0 + wn + nt * 8 + t4 * 2;
#pragma unroll
            for (int half = 0; half < 2; half++) {
                const int r = m0 + wm + mt * 16 + grp + half * 8;
                float2 o;
                o.x = acc[mt][nt][half * 2 + 0] + __ldg(bp + c);
                o.y = acc[mt][nt][half * 2 + 1] + __ldg(bp + c + 1);
                *(float2*)(out + ((size_t)r << 10) + c) = o;
            }
        }
    }
}

// ---------------------------------------------------------------------------
extern "C" void kernel_launch(void* const* d_in, const int* in_sizes, int n_in,
                              void* d_out, int out_size)
{
    const float* x     = (const float*)d_in[0];  // [B,N,C]
    const float* im    = (const float*)d_in[1];  // [B,H,N,N]
    const float* mask  = (const float*)d_in[2];  // [B,1,N,N]
    const float* Wqkv  = (const float*)d_in[3];  // [C,3C]
    const float* bqkv  = (const float*)d_in[4];  // [3C]
    const float* Wproj = (const float*)d_in[5];  // [C,C]
    const float* bproj = (const float*)d_in[6];  // [C]

    float* out  = (float*)d_out;                 // [B,N,C]
    float* attn = out + OUT_ELEMS;               // [B,H,N,N]

    (void)in_sizes; (void)n_in; (void)out_size;

    qkv_tc<<<dim3(NQKV / 128, M1 / 128), 256>>>(x, Wqkv, bqkv);
    qk_tc<<<dim3(Nn / 128, Nn / 128, BH), 256>>>(im, mask, attn);
    softmax_rows<<<(unsigned)(BH * Nn), 256>>>(attn);
    av_tc<<<dim3(Nn / 128, BH), 256>>>(attn);
    proj_tc<<<dim3(Cc / 128, M1 / 128), 256>>>(Wproj, bproj, out);
}

// round 12
// speedup vs baseline: 1.0046x; 1.0000x over previous
#include <cuda_runtime.h>
#include <math_constants.h>
#include <cstdint>

// Problem constants
constexpr int Bc = 4;
constexpr int Nn = 1024;
constexpr int Cc = 1024;
constexpr int Hh = 16;
constexpr int Dd = 64;          // head dim
constexpr int BH = Bc * Hh;     // 64
constexpr int M1 = Bc * Nn;     // 4096 rows of x
constexpr int NQKV = 3 * Cc;    // 3072

constexpr size_t QKV_ELEMS = (size_t)BH * Nn * Dd;   // 4,194,304 per tensor
constexpr size_t OUT_ELEMS = (size_t)Bc * Nn * Cc;   // 4,194,304

// Scratch (device globals — no allocations allowed)
__device__ float g_q[QKV_ELEMS];
__device__ float g_k[QKV_ELEMS];
__device__ float g_v[QKV_ELEMS];
__device__ float g_oh[OUT_ELEMS];   // merged heads [B, N, C]

// ---------------------------------------------------------------------------
// TF32 helpers: 3xTF32 decomposition for fp32-accurate tensor-core GEMM.
// ---------------------------------------------------------------------------
__device__ __forceinline__ uint32_t cvt_tf32(float x) {
    uint32_t r;
    asm("cvt.rna.tf32.f32 %0, %1;" : "=r"(r) : "f"(x));
    return r;
}
__device__ __forceinline__ void split_tf32(float x, uint32_t& h, uint32_t& l) {
    h = cvt_tf32(x);
    l = cvt_tf32(x - __uint_as_float(h));
}
__device__ __forceinline__ void split4(float4 v, uint4& h, uint4& l) {
    split_tf32(v.x, h.x, l.x);
    split_tf32(v.y, h.y, l.y);
    split_tf32(v.z, h.z, l.z);
    split_tf32(v.w, h.w, l.w);
}
__device__ __forceinline__ void mma8(float* d,
                                     uint32_t a0, uint32_t a1, uint32_t a2, uint32_t a3,
                                     uint32_t b0, uint32_t b1) {
    asm volatile(
        "mma.sync.aligned.m16n8k8.row.col.f32.tf32.tf32.f32 "
        "{%0,%1,%2,%3}, {%4,%5,%6,%7}, {%8,%9}, {%0,%1,%2,%3};\n"
        : "+f"(d[0]), "+f"(d[1]), "+f"(d[2]), "+f"(d[3])
        : "r"(a0), "r"(a1), "r"(a2), "r"(a3), "r"(b0), "r"(b1));
}

// ---------------------------------------------------------------------------
// Kernel 1: QKV GEMM (3xTF32).  X[4096,1024] @ W[1024,3072] + b ->
// scatter into Q(scaled)/K/V laid out [BH, N, HD].
// Block tile 128x128, BK=16, 256 threads (8 warps, 2x4), warp tile 64x32.
// ---------------------------------------------------------------------------
__device__ __forceinline__ void qkv_store(int m, int n, float v,
                                          const float* __restrict__ bias) {
    v += __ldg(bias + n);
    const int b = m >> 10, nn = m & 1023;
    const int part = n >> 10, w = n & 1023;
    const int h = w >> 6, d = w & 63;
    const size_t idx = (((size_t)(b * Hh + h)) * Nn + nn) * Dd + d;
    if (part == 0)      g_q[idx] = v * 0.125f;    // HD^-0.5
    else if (part == 1) g_k[idx] = v;
    else                g_v[idx] = v;
}

__global__ __launch_bounds__(256) void qkv_tc(const float* __restrict__ X,
                                              const float* __restrict__ W,
                                              const float* __restrict__ bias)
{
    __shared__ uint32_t AsH[128][20], AsL[128][20];
    __shared__ uint32_t BsH[16][136], BsL[16][136];
    const int tid = threadIdx.x;
    const int m0 = blockIdx.y * 128, n0 = blockIdx.x * 128;

    const int a_m = tid >> 2, a_k4 = tid & 3;     // A: rows a_m, a_m+64
    const int b_k = tid >> 5, b_n4 = tid & 31;    // B: rows b_k, b_k+8

    float4 ra0 = *(const float4*)(X + (size_t)(m0 + a_m) * Cc + a_k4 * 4);
    float4 ra1 = *(const float4*)(X + (size_t)(m0 + a_m + 64) * Cc + a_k4 * 4);
    float4 rb0 = *(const float4*)(W + (size_t)b_k * NQKV + n0 + b_n4 * 4);
    float4 rb1 = *(const float4*)(W + (size_t)(b_k + 8) * NQKV + n0 + b_n4 * 4);
    {
        uint4 h, l;
        split4(ra0, h, l); *(uint4*)&AsH[a_m][a_k4 * 4] = h;      *(uint4*)&AsL[a_m][a_k4 * 4] = l;
        split4(ra1, h, l); *(uint4*)&AsH[a_m + 64][a_k4 * 4] = h; *(uint4*)&AsL[a_m + 64][a_k4 * 4] = l;
        split4(rb0, h, l); *(uint4*)&BsH[b_k][b_n4 * 4] = h;      *(uint4*)&BsL[b_k][b_n4 * 4] = l;
        split4(rb1, h, l); *(uint4*)&BsH[b_k + 8][b_n4 * 4] = h;  *(uint4*)&BsL[b_k + 8][b_n4 * 4] = l;
    }
    __syncthreads();

    const int lane = tid & 31, wid = tid >> 5;
    const int grp = lane >> 2, t4 = lane & 3;
    const int wm = (wid >> 2) * 64, wn = (wid & 3) * 32;

    float acc[4][4][4];
#pragma unroll
    for (int i = 0; i < 4; i++)
#pragma unroll
        for (int j = 0; j < 4; j++)
#pragma unroll
            for (int c = 0; c < 4; c++) acc[i][j][c] = 0.0f;

#pragma unroll 1
    for (int k0 = 0; k0 < Cc; k0 += 16) {
        const bool nxt = (k0 + 16) < Cc;
        if (nxt) {
            ra0 = *(const float4*)(X + (size_t)(m0 + a_m) * Cc + k0 + 16 + a_k4 * 4);
            ra1 = *(const float4*)(X + (size_t)(m0 + a_m + 64) * Cc + k0 + 16 + a_k4 * 4);
            rb0 = *(const float4*)(W + (size_t)(k0 + 16 + b_k) * NQKV + n0 + b_n4 * 4);
            rb1 = *(const float4*)(W + (size_t)(k0 + 16 + b_k + 8) * NQKV + n0 + b_n4 * 4);
        }
#pragma unroll
        for (int kk = 0; kk < 2; kk++) {
            uint32_t bh[4][2], bl[4][2];
#pragma unroll
            for (int nt = 0; nt < 4; nt++) {
                const int n = wn + nt * 8 + grp;
                bh[nt][0] = BsH[kk * 8 + t4][n];     bh[nt][1] = BsH[kk * 8 + t4 + 4][n];
                bl[nt][0] = BsL[kk * 8 + t4][n];     bl[nt][1] = BsL[kk * 8 + t4 + 4][n];
            }
#pragma unroll
            for (int mt = 0; mt < 4; mt++) {
                const int r = wm + mt * 16 + grp;
                const uint32_t ah0 = AsH[r][kk * 8 + t4],     ah1 = AsH[r + 8][kk * 8 + t4];
                const uint32_t ah2 = AsH[r][kk * 8 + t4 + 4], ah3 = AsH[r + 8][kk * 8 + t4 + 4];
                const uint32_t al0 = AsL[r][kk * 8 + t4],     al1 = AsL[r + 8][kk * 8 + t4];
                const uint32_t al2 = AsL[r][kk * 8 + t4 + 4], al3 = AsL[r + 8][kk * 8 + t4 + 4];
#pragma unroll
                for (int nt = 0; nt < 4; nt++) {
                    mma8(acc[mt][nt], al0, al1, al2, al3, bh[nt][0], bh[nt][1]);
                    mma8(acc[mt][nt], ah0, ah1, ah2, ah3, bl[nt][0], bl[nt][1]);
                    mma8(acc[mt][nt], ah0, ah1, ah2, ah3, bh[nt][0], bh[nt][1]);
                }
            }
        }
        if (nxt) {
            __syncthreads();
            uint4 h, l;
            split4(ra0, h, l); *(uint4*)&AsH[a_m][a_k4 * 4] = h;      *(uint4*)&AsL[a_m][a_k4 * 4] = l;
            split4(ra1, h, l); *(uint4*)&AsH[a_m + 64][a_k4 * 4] = h; *(uint4*)&AsL[a_m + 64][a_k4 * 4] = l;
            split4(rb0, h, l); *(uint4*)&BsH[b_k][b_n4 * 4] = h;      *(uint4*)&BsL[b_k][b_n4 * 4] = l;
            split4(rb1, h, l); *(uint4*)&BsH[b_k + 8][b_n4 * 4] = h;  *(uint4*)&BsL[b_k + 8][b_n4 * 4] = l;
            __syncthreads();
        }
    }

#pragma unroll
    for (int mt = 0; mt < 4; mt++) {
        const int r = m0 + wm + mt * 16 + grp;
#pragma unroll
        for (int nt = 0; nt < 4; nt++) {
            const int c = n0 + wn + nt * 8 + t4 * 2;
            qkv_store(r,     c,     acc[mt][nt][0], bias);
            qkv_store(r,     c + 1, acc[mt][nt][1], bias);
            qkv_store(r + 8, c,     acc[mt][nt][2], bias);
            qkv_store(r + 8, c + 1, acc[mt][nt][3], bias);
        }
    }
}

// ---------------------------------------------------------------------------
// Kernel 2: logits (3xTF32) = Q @ K^T + int_matrix + (1-mask)*-1e9.
// Per (b,h): [1024,64]@[64,1024].  Block 128x128, K=64 in 4 stages of 16.
// ---------------------------------------------------------------------------
__global__ __launch_bounds__(256) void qk_tc(const float* __restrict__ IM,
                                             const float* __restrict__ MASK,
                                             float* __restrict__ attn)
{
    __shared__ uint32_t AsH[128][20], AsL[128][20];
    __shared__ uint32_t KsH[128][20], KsL[128][20];
    const int z = blockIdx.z;
    const int m0 = blockIdx.y * 128, n0 = blockIdx.x * 128;
    const float* Qb = g_q + (size_t)z * Nn * Dd;
    const float* Kb = g_k + (size_t)z * Nn * Dd;
    const int tid = threadIdx.x;

    const int a_m = tid >> 2, a_k4 = tid & 3;   // rows a_m, a_m+64 of the 128-tile

    float4 ra0 = *(const float4*)(Qb + (size_t)(m0 + a_m) * Dd + a_k4 * 4);
    float4 ra1 = *(const float4*)(Qb + (size_t)(m0 + a_m + 64) * Dd + a_k4 * 4);
    float4 rk0 = *(const float4*)(Kb + (size_t)(n0 + a_m) * Dd + a_k4 * 4);
    float4 rk1 = *(const float4*)(Kb + (size_t)(n0 + a_m + 64) * Dd + a_k4 * 4);
    {
        uint4 h, l;
        split4(ra0, h, l); *(uint4*)&AsH[a_m][a_k4 * 4] = h;      *(uint4*)&AsL[a_m][a_k4 * 4] = l;
        split4(ra1, h, l); *(uint4*)&AsH[a_m + 64][a_k4 * 4] = h; *(uint4*)&AsL[a_m + 64][a_k4 * 4] = l;
        split4(rk0, h, l); *(uint4*)&KsH[a_m][a_k4 * 4] = h;      *(uint4*)&KsL[a_m][a_k4 * 4] = l;
        split4(rk1, h, l); *(uint4*)&KsH[a_m + 64][a_k4 * 4] = h; *(uint4*)&KsL[a_m + 64][a_k4 * 4] = l;
    }
    __syncthreads();

    const int lane = tid & 31, wid = tid >> 5;
    const int grp = lane >> 2, t4 = lane & 3;
    const int wm = (wid >> 2) * 64, wn = (wid & 3) * 32;

    float acc[4][4][4];
#pragma unroll
    for (int i = 0; i < 4; i++)
#pragma unroll
        for (int j = 0; j < 4; j++)
#pragma unroll
            for (int c = 0; c < 4; c++) acc[i][j][c] = 0.0f;

#pragma unroll 1
    for (int k0 = 0; k0 < Dd; k0 += 16) {
        const bool nxt = (k0 + 16) < Dd;
        if (nxt) {
            ra0 = *(const float4*)(Qb + (size_t)(m0 + a_m) * Dd + k0 + 16 + a_k4 * 4);
            ra1 = *(const float4*)(Qb + (size_t)(m0 + a_m + 64) * Dd + k0 + 16 + a_k4 * 4);
            rk0 = *(const float4*)(Kb + (size_t)(n0 + a_m) * Dd + k0 + 16 + a_k4 * 4);
            rk1 = *(const float4*)(Kb + (size_t)(n0 + a_m + 64) * Dd + k0 + 16 + a_k4 * 4);
        }
#pragma unroll
        for (int kk = 0; kk < 2; kk++) {
            uint32_t bh[4][2], bl[4][2];
#pragma unroll
            for (int nt = 0; nt < 4; nt++) {
                const int n = wn + nt * 8 + grp;
                bh[nt][0] = KsH[n][kk * 8 + t4];     bh[nt][1] = KsH[n][kk * 8 + t4 + 4];
                bl[nt][0] = KsL[n][kk * 8 + t4];     bl[nt][1] = KsL[n][kk * 8 + t4 + 4];
            }
#pragma unroll
            for (int mt = 0; mt < 4; mt++) {
                const int r = wm + mt * 16 + grp;
                const uint32_t ah0 = AsH[r][kk * 8 + t4],     ah1 = AsH[r + 8][kk * 8 + t4];
                const uint32_t ah2 = AsH[r][kk * 8 + t4 + 4], ah3 = AsH[r + 8][kk * 8 + t4 + 4];
                const uint32_t al0 = AsL[r][kk * 8 + t4],     al1 = AsL[r + 8][kk * 8 + t4];
                const uint32_t al2 = AsL[r][kk * 8 + t4 + 4], al3 = AsL[r + 8][kk * 8 + t4 + 4];
#pragma unroll
                for (int nt = 0; nt < 4; nt++) {
                    mma8(acc[mt][nt], al0, al1, al2, al3, bh[nt][0], bh[nt][1]);
                    mma8(acc[mt][nt], ah0, ah1, ah2, ah3, bl[nt][0], bl[nt][1]);
                    mma8(acc[mt][nt], ah0, ah1, ah2, ah3, bh[nt][0], bh[nt][1]);
                }
            }
        }
        if (nxt) {
            __syncthreads();
            uint4 h, l;
            split4(ra0, h, l); *(uint4*)&AsH[a_m][a_k4 * 4] = h;      *(uint4*)&AsL[a_m][a_k4 * 4] = l;
            split4(ra1, h, l); *(uint4*)&AsH[a_m + 64][a_k4 * 4] = h; *(uint4*)&AsL[a_m + 64][a_k4 * 4] = l;
            split4(rk0, h, l); *(uint4*)&KsH[a_m][a_k4 * 4] = h;      *(uint4*)&KsL[a_m][a_k4 * 4] = l;
            split4(rk1, h, l); *(uint4*)&KsH[a_m + 64][a_k4 * 4] = h; *(uint4*)&KsL[a_m + 64][a_k4 * 4] = l;
            __syncthreads();
        }
    }

    const int b = z >> 4;
    const float* imz = IM + ((size_t)z << 20);
    const float* mkb = MASK + ((size_t)b << 20);
    float* az = attn + ((size_t)z << 20);
#pragma unroll
    for (int mt = 0; mt < 4; mt++) {
#pragma unroll
        for (int nt = 0; nt < 4; nt++) {
            const int c = n0 + wn + nt * 8 + t4 * 2;
#pragma unroll
            for (int half = 0; half < 2; half++) {
                const int r = m0 + wm + mt * 16 + grp + half * 8;
                const size_t off = ((size_t)r << 10) + c;
                const float2 im2 = *(const float2*)(imz + off);
                const float2 mk2 = *(const float2*)(mkb + off);
                float2 o;
                o.x = acc[mt][nt][half * 2 + 0] + im2.x + (1.0f - mk2.x) * -1e9f;
                o.y = acc[mt][nt][half * 2 + 1] + im2.y + (1.0f - mk2.y) * -1e9f;
                *(float2*)(az + off) = o;
            }
        }
    }
}

// ---------------------------------------------------------------------------
// Kernel 3: row softmax over 1024 elements, in place.  One block per row.
// ---------------------------------------------------------------------------
__device__ __forceinline__ float warpMax(float v) {
#pragma unroll
    for (int o = 16; o; o >>= 1) v = fmaxf(v, __shfl_xor_sync(0xffffffffu, v, o));
    return v;
}
__device__ __forceinline__ float warpSum(float v) {
#pragma unroll
    for (int o = 16; o; o >>= 1) v += __shfl_xor_sync(0xffffffffu, v, o);
    return v;
}

__global__ __launch_bounds__(256) void softmax_rows(float* __restrict__ attn)
{
    __shared__ float sm[8];
    __shared__ float ss[8];
    const size_t row = blockIdx.x;
    float4* p = (float4*)(attn + row * Nn);
    const int tid = threadIdx.x;
    const int lane = tid & 31, wid = tid >> 5;

    float4 v = p[tid];
    float m = fmaxf(fmaxf(v.x, v.y), fmaxf(v.z, v.w));
    m = warpMax(m);
    if (lane == 0) sm[wid] = m;
    __syncthreads();
    if (tid < 32) {
        float t = (tid < 8) ? sm[tid] : -CUDART_INF_F;
        t = warpMax(t);
        if (tid == 0) sm[0] = t;
    }
    __syncthreads();
    m = sm[0];

    float4 e;
    e.x = expf(v.x - m);
    e.y = expf(v.y - m);
    e.z = expf(v.z - m);
    e.w = expf(v.w - m);
    float s = e.x + e.y + e.z + e.w;
    s = warpSum(s);
    if (lane == 0) ss[wid] = s;
    __syncthreads();
    if (tid < 32) {
        float t = (tid < 8) ? ss[tid] : 0.0f;
        t = warpSum(t);
        if (tid == 0) ss[0] = t;
    }
    __syncthreads();
    const float inv = 1.0f / ss[0];
    e.x *= inv; e.y *= inv; e.z *= inv; e.w *= inv;
    p[tid] = e;
}

// ---------------------------------------------------------------------------
// Kernel 4: out_heads = attn @ V (3xTF32).  Per (b,h): [1024,1024]@[1024,64].
// Block 128x64, BK=16, 8 warps (4x2), warp tile 32x32.
// ---------------------------------------------------------------------------
__global__ __launch_bounds__(256) void av_tc(const float* __restrict__ attn)
{
    __shared__ uint32_t AsH[128][20], AsL[128][20];
    __shared__ uint32_t BsH[16][72], BsL[16][72];
    const int z = blockIdx.y;
    const int r0 = blockIdx.x * 128;
    const float* Ab = attn + ((size_t)z << 20);
    const float* Vb = g_v + (size_t)z * Nn * Dd;
    const int tid = threadIdx.x;

    const int a_m = tid >> 2, a_k4 = tid & 3;   // A rows a_m, a_m+64
    const int v_k = tid >> 4, v_n4 = tid & 15;  // V row v_k (16 rows x 16 float4)

    float4 ra0 = *(const float4*)(Ab + ((size_t)(r0 + a_m) << 10) + a_k4 * 4);
    float4 ra1 = *(const float4*)(Ab + ((size_t)(r0 + a_m + 64) << 10) + a_k4 * 4);
    float4 rb0 = *(const float4*)(Vb + (size_t)v_k * Dd + v_n4 * 4);
    {
        uint4 h, l;
        split4(ra0, h, l); *(uint4*)&AsH[a_m][a_k4 * 4] = h;      *(uint4*)&AsL[a_m][a_k4 * 4] = l;
        split4(ra1, h, l); *(uint4*)&AsH[a_m + 64][a_k4 * 4] = h; *(uint4*)&AsL[a_m + 64][a_k4 * 4] = l;
        split4(rb0, h, l); *(uint4*)&BsH[v_k][v_n4 * 4] = h;      *(uint4*)&BsL[v_k][v_n4 * 4] = l;
    }
    __syncthreads();

    const int lane = tid & 31, wid = tid >> 5;
    const int grp = lane >> 2, t4 = lane & 3;
    const int wm = (wid >> 1) * 32, wn = (wid & 1) * 32;

    float acc[2][4][4];
#pragma unroll
    for (int i = 0; i < 2; i++)
#pragma unroll
        for (int j = 0; j < 4; j++)
#pragma unroll
            for (int c = 0; c < 4; c++) acc[i][j][c] = 0.0f;

#pragma unroll 1
    for (int k0 = 0; k0 < Nn; k0 += 16) {
        const bool nxt = (k0 + 16) < Nn;
        if (nxt) {
            ra0 = *(const float4*)(Ab + ((size_t)(r0 + a_m) << 10) + k0 + 16 + a_k4 * 4);
            ra1 = *(const float4*)(Ab + ((size_t)(r0 + a_m + 64) << 10) + k0 + 16 + a_k4 * 4);
            rb0 = *(const float4*)(Vb + (size_t)(k0 + 16 + v_k) * Dd + v_n4 * 4);
        }
#pragma unroll
        for (int kk = 0; kk < 2; kk++) {
            uint32_t bh[4][2], bl[4][2];
#pragma unroll
            for (int nt = 0; nt < 4; nt++) {
                const int n = wn + nt * 8 + grp;
                bh[nt][0] = BsH[kk * 8 + t4][n];     bh[nt][1] = BsH[kk * 8 + t4 + 4][n];
                bl[nt][0] = BsL[kk * 8 + t4][n];     bl[nt][1] = BsL[kk * 8 + t4 + 4][n];
            }
#pragma unroll
            for (int mt = 0; mt < 2; mt++) {
                const int r = wm + mt * 16 + grp;
                const uint32_t ah0 = AsH[r][kk * 8 + t4],     ah1 = AsH[r + 8][kk * 8 + t4];
                const uint32_t ah2 = AsH[r][kk * 8 + t4 + 4], ah3 = AsH[r + 8][kk * 8 + t4 + 4];
                const uint32_t al0 = AsL[r][kk * 8 + t4],     al1 = AsL[r + 8][kk * 8 + t4];
                const uint32_t al2 = AsL[r][kk * 8 + t4 + 4], al3 = AsL[r + 8][kk * 8 + t4 + 4];
#pragma unroll
                for (int nt = 0; nt < 4; nt++) {
                    mma8(acc[mt][nt], al0, al1, al2, al3, bh[nt][0], bh[nt][1]);
                    mma8(acc[mt][nt], ah0, ah1, ah2, ah3, bl[nt][0], bl[nt][1]);
                    mma8(acc[mt][nt], ah0, ah1, ah2, ah3, bh[nt][0], bh[nt][1]);
                }
            }
        }
        if (nxt) {
            __syncthreads();
            uint4 h, l;
            split4(ra0, h, l); *(uint4*)&AsH[a_m][a_k4 * 4] = h;      *(uint4*)&AsL[a_m][a_k4 * 4] = l;
            split4(ra1, h, l); *(uint4*)&AsH[a_m + 64][a_k4 * 4] = h; *(uint4*)&AsL[a_m + 64][a_k4 * 4] = l;
            split4(rb0, h, l); *(uint4*)&BsH[v_k][v_n4 * 4] = h;      *(uint4*)&BsL[v_k][v_n4 * 4] = l;
            __syncthreads();
        }
    }

    const int b = z >> 4, h = z & 15;
#pragma unroll
    for (int mt = 0; mt < 2; mt++) {
#pragma unroll
        for (int nt = 0; nt < 4; nt++) {
            const int d = wn + nt * 8 + t4 * 2;
#pragma unroll
            for (int half = 0; half < 2; half++) {
                const int r = r0 + wm + mt * 16 + grp + half * 8;
                float2 o;
                o.x = acc[mt][nt][half * 2 + 0];
                o.y = acc[mt][nt][half * 2 + 1];
                *(float2*)(g_oh + ((size_t)(b * Nn + r) << 10) + h * Dd + d) = o;
            }
        }
    }
}

// ---------------------------------------------------------------------------
// Kernel 5: final projection (3xTF32).  OH[4096,1024] @ Wp[1024,1024] + bp.
// Same structure as kernel 1, N=1024.
// ---------------------------------------------------------------------------
__global__ __launch_bounds__(256) void proj_tc(const float* __restrict__ Wp,
                                               const float* __restrict__ bp,
                                               float* __restrict__ out)
{
    __shared__ uint32_t AsH[128][20], AsL[128][20];
    __shared__ uint32_t BsH[16][136], BsL[16][136];
    const int tid = threadIdx.x;
    const int m0 = blockIdx.y * 128, n0 = blockIdx.x * 128;

    const int a_m = tid >> 2, a_k4 = tid & 3;
    const int b_k = tid >> 5, b_n4 = tid & 31;

    float4 ra0 = *(const float4*)(g_oh + (size_t)(m0 + a_m) * Cc + a_k4 * 4);
    float4 ra1 = *(const float4*)(g_oh + (size_t)(m0 + a_m + 64) * Cc + a_k4 * 4);
    float4 rb0 = *(const float4*)(Wp + (size_t)b_k * Cc + n0 + b_n4 * 4);
    float4 rb1 = *(const float4*)(Wp + (size_t)(b_k + 8) * Cc + n0 + b_n4 * 4);
    {
        uint4 h, l;
        split4(ra0, h, l); *(uint4*)&AsH[a_m][a_k4 * 4] = h;      *(uint4*)&AsL[a_m][a_k4 * 4] = l;
        split4(ra1, h, l); *(uint4*)&AsH[a_m + 64][a_k4 * 4] = h; *(uint4*)&AsL[a_m + 64][a_k4 * 4] = l;
        split4(rb0, h, l); *(uint4*)&BsH[b_k][b_n4 * 4] = h;      *(uint4*)&BsL[b_k][b_n4 * 4] = l;
        split4(rb1, h, l); *(uint4*)&BsH[b_k + 8][b_n4 * 4] = h;  *(uint4*)&BsL[b_k + 8][b_n4 * 4] = l;
    }
    __syncthreads();

    const int lane = tid & 31, wid = tid >> 5;
    const int grp = lane >> 2, t4 = lane & 3;
    const int wm = (wid >> 2) * 64, wn = (wid & 3) * 32;

    float acc[4][4][4];
#pragma unroll
    for (int i = 0; i < 4; i++)
#pragma unroll
        for (int j = 0; j < 4; j++)
#pragma unroll
            for (int c = 0; c < 4; c++) acc[i][j][c] = 0.0f;

#pragma unroll 1
    for (int k0 = 0; k0 < Cc; k0 += 16) {
        const bool nxt = (k0 + 16) < Cc;
        if (nxt) {
            ra0 = *(const float4*)(g_oh + (size_t)(m0 + a_m) * Cc + k0 + 16 + a_k4 * 4);
            ra1 = *(const float4*)(g_oh + (size_t)(m0 + a_m + 64) * Cc + k0 + 16 + a_k4 * 4);
            rb0 = *(const float4*)(Wp + (size_t)(k0 + 16 + b_k) * Cc + n0 + b_n4 * 4);
            rb1 = *(const float4*)(Wp + (size_t)(k0 + 16 + b_k + 8) * Cc + n0 + b_n4 * 4);
        }
#pragma unroll
        for (int kk = 0; kk < 2; kk++) {
            uint32_t bh[4][2], bl[4][2];
#pragma unroll
            for (int nt = 0; nt < 4; nt++) {
                const int n = wn + nt * 8 + grp;
                bh[nt][0] = BsH[kk * 8 + t4][n];     bh[nt][1] = BsH[kk * 8 + t4 + 4][n];
                bl[nt][0] = BsL[kk * 8 + t4][n];     bl[nt][1] = BsL[kk * 8 + t4 + 4][n];
            }
#pragma unroll
            for (int mt = 0; mt < 4; mt++) {
                const int r = wm + mt * 16 + grp;
                const uint32_t ah0 = AsH[r][kk * 8 + t4],     ah1 = AsH[r + 8][kk * 8 + t4];
                const uint32_t ah2 = AsH[r][kk * 8 + t4 + 4], ah3 = AsH[r + 8][kk * 8 + t4 + 4];
                const uint32_t al0 = AsL[r][kk * 8 + t4],     al1 = AsL[r + 8][kk * 8 + t4];
                const uint32_t al2 = AsL[r][kk * 8 + t4 + 4], al3 = AsL[r + 8][kk * 8 + t4 + 4];
#pragma unroll
                for (int nt = 0; nt < 4; nt++) {
                    mma8(acc[mt][nt], al0, al1, al2, al3, bh[nt][0], bh[nt][1]);
                    mma8(acc[mt][nt], ah0, ah1, ah2, ah3, bl[nt][0], bl[nt][1]);
                    mma8(acc[mt][nt], ah0, ah1, ah2, ah3, bh[nt][0], bh[nt][1]);
                }
            }
        }
        if (nxt) {
            __syncthreads();
            uint4 h, l;
            split4(ra0, h, l); *(uint4*)&AsH[a_m][a_k4 * 4] = h;      *(uint4*)&AsL[a_m][a_k4 * 4] = l;
            split4(ra1, h, l); *(uint4*)&AsH[a_m + 64][a_k4 * 4] = h; *(uint4*)&AsL[a_m + 64][a_k4 * 4] = l;
            split4(rb0, h, l); *(uint4*)&BsH[b_k][b_n4 * 4] = h;      *(uint4*)&BsL[b_k][b_n4 * 4] = l;
            split4(rb1, h, l); *(uint4*)&BsH[b_k + 8][b_n4 * 4] = h;  *(uint4*)&BsL[b_k + 8][b_n4 * 4] = l;
            __syncthreads();
        }
    }

#pragma unroll
    for (int mt = 0; mt < 4; mt++) {
#pragma unroll
        for (int nt = 0; nt < 4; nt++) {
            const int c = n0 + wn + nt * 8 + t4 * 2;
#pragma unroll
            for (int half = 0; half < 2; half++) {
                const int r = m0 + wm + mt * 16 + grp + half * 8;
                float2 o;
                o.x = acc[mt][nt][half * 2 + 0] + __ldg(bp + c);
                o.y = acc[mt][nt][half * 2 + 1] + __ldg(bp + c + 1);
                *(float2*)(out + ((size_t)r << 10) + c) = o;
            }
        }
    }
}

// ---------------------------------------------------------------------------
extern "C" void kernel_launch(void* const* d_in, const int* in_sizes, int n_in,
                              void* d_out, int out_size)
{
    const float* x     = (const float*)d_in[0];  // [B,N,C]
    const float* im    = (const float*)d_in[1];  // [B,H,N,N]
    const float* mask  = (const float*)d_in[2];  // [B,1,N,N]
    const float* Wqkv  = (const float*)d_in[3];  // [C,3C]
    const float* bqkv  = (const float*)d_in[4];  // [3C]
    const float* Wproj = (const float*)d_in[5];  // [C,C]
    const float* bproj = (const float*)d_in[6];  // [C]

    float* out  = (float*)d_out;                 // [B,N,C]
    float* attn = out + OUT_ELEMS;               // [B,H,N,N]

    (void)in_sizes; (void)n_in; (void)out_size;

    qkv_tc<<<dim3(NQKV / 128, M1 / 128), 256>>>(x, Wqkv, bqkv);
    qk_tc<<<dim3(Nn / 128, Nn / 128, BH), 256>>>(im, mask, attn);
    softmax_rows<<<(unsigned)(BH * Nn), 256>>>(attn);
    av_tc<<<dim3(Nn / 128, BH), 256>>>(attn);
    proj_tc<<<dim3(Cc / 128, M1 / 128), 256>>>(Wproj, bproj, out);
}